// round 5
// baseline (speedup 1.0000x reference)
#include <cuda_runtime.h>
#include <math.h>

// ---------------- scratch (static device memory; no allocations) ----------------
#define BB 128
#define TT 46
#define VV 8150
#define EE 300
#define HH 128
#define MROWS (BB*TT)   // 5888

__device__ float g_e [2][MROWS*EE];    // embeddings output [5888,300]
__device__ float g_xz[2][MROWS*512];   // x-part of gates   [5888,512]
__device__ float g_o [2][MROWS*HH];    // lstm outputs      [b*46+t,128]
__device__ float g_a [2][BB*512];      // attention outputs [128,512]

// ---------------- f32x2 helpers ----------------
__device__ __forceinline__ unsigned long long ffma2(unsigned long long a,
                                                    unsigned long long b,
                                                    unsigned long long c) {
    unsigned long long d;
    asm("fma.rn.f32x2 %0, %1, %2, %3;" : "=l"(d) : "l"(a), "l"(b), "l"(c));
    return d;
}
__device__ __forceinline__ unsigned long long pack2(float x, float y) {
    unsigned long long d;
    asm("mov.b64 %0, {%1, %2};" : "=l"(d) : "r"(__float_as_uint(x)), "r"(__float_as_uint(y)));
    return d;
}
__device__ __forceinline__ float2 unpack2(unsigned long long v) {
    unsigned int lo, hi;
    asm("mov.b64 {%0, %1}, %2;" : "=r"(lo), "=r"(hi) : "l"(v));
    return make_float2(__uint_as_float(lo), __uint_as_float(hi));
}
__device__ __forceinline__ float sigm(float x) { return 1.0f / (1.0f + expf(-x)); }

// ---------------- generic fp32 GEMM: C = A @ B ----------------
// BM=128, BN=128, BK=8, 256 threads, 8x8 per thread, f32x2 accumulators.
// mode 0: A = x{1,2} (ext), B = embed{1,2} (ext), C = g_e[z]
// mode 1: A = g_e[z],       B = W_lstm{1,2} rows 0..299, C = g_xz[z]

__device__ __forceinline__ void gemm_load_regs(
    const float* __restrict__ A, const float* __restrict__ Bm,
    int N, int K, int lda, int ldb,
    int m0, int n0, int k0, int tid, float2 av[2], float4& bv)
{
#pragma unroll
    for (int j = 0; j < 2; j++) {
        int l  = tid + 256 * j;
        int am = l >> 2;
        int ak = (l & 3) * 2;
        int k  = k0 + ak;
        float2 v = make_float2(0.f, 0.f);
        const float* p = A + (size_t)(m0 + am) * lda + k;
        if (k + 1 < K)      v = *(const float2*)p;
        else if (k < K)     v.x = *p;
        av[j] = v;
    }
    int bk = tid >> 5, bn = (tid & 31) * 4;
    int k = k0 + bk, n = n0 + bn;
    float4 v = make_float4(0.f, 0.f, 0.f, 0.f);
    if (k < K) {
        const float* p = Bm + (size_t)k * ldb + n;
        if (n + 3 < N) v = *(const float4*)p;
        else {
            if (n     < N) v.x = p[0];
            if (n + 1 < N) v.y = p[1];
            if (n + 2 < N) v.z = p[2];
        }
    }
    bv = v;
}

__device__ __forceinline__ void gemm_store_smem(
    float (*As)[132], float (*Bs)[128], int tid, const float2 av[2], const float4& bv)
{
#pragma unroll
    for (int j = 0; j < 2; j++) {
        int l  = tid + 256 * j;
        int am = l >> 2;
        int ak = (l & 3) * 2;
        As[ak][am]     = av[j].x;
        As[ak + 1][am] = av[j].y;
    }
    int bk = tid >> 5, bn = (tid & 31) * 4;
    *(float4*)&Bs[bk][bn] = bv;
}

__global__ __launch_bounds__(256)
void gemm_kernel(const float* __restrict__ Aext0, const float* __restrict__ Aext1,
                 const float* __restrict__ Bv0,  const float* __restrict__ Bv1,
                 int M, int N, int K, int lda, int ldb, int ldc, int mode)
{
    int z = blockIdx.z;
    const float* A  = (mode == 0) ? (z ? Aext1 : Aext0) : g_e[z];
    const float* Bm = z ? Bv1 : Bv0;
    float* C = (mode == 0) ? g_e[z] : g_xz[z];

    __shared__ float As[2][8][132];
    __shared__ float Bs[2][8][128];

    int tid = threadIdx.x;
    int tx = tid & 15, ty = tid >> 4;
    int m0 = blockIdx.y * 128;
    int n0 = blockIdx.x * 128;

    unsigned long long acc[8][4];
#pragma unroll
    for (int i = 0; i < 8; i++)
#pragma unroll
        for (int j = 0; j < 4; j++) acc[i][j] = 0ULL;

    int numK = (K + 7) / 8;

    float2 av[2]; float4 bv;
    gemm_load_regs(A, Bm, N, K, lda, ldb, m0, n0, 0, tid, av, bv);
    gemm_store_smem(As[0], Bs[0], tid, av, bv);
    __syncthreads();

    for (int kt = 0; kt < numK; kt++) {
        int cur = kt & 1;
        bool hn = (kt + 1) < numK;
        if (hn) gemm_load_regs(A, Bm, N, K, lda, ldb, m0, n0, (kt + 1) * 8, tid, av, bv);

#pragma unroll
        for (int kk = 0; kk < 8; kk++) {
            float4 a0 = *(const float4*)&As[cur][kk][ty * 8];
            float4 a1 = *(const float4*)&As[cur][kk][ty * 8 + 4];
            float4 b0 = *(const float4*)&Bs[cur][kk][tx * 8];
            float4 b1 = *(const float4*)&Bs[cur][kk][tx * 8 + 4];
            unsigned long long bb[4];
            bb[0] = pack2(b0.x, b0.y); bb[1] = pack2(b0.z, b0.w);
            bb[2] = pack2(b1.x, b1.y); bb[3] = pack2(b1.z, b1.w);
            float am[8] = {a0.x, a0.y, a0.z, a0.w, a1.x, a1.y, a1.z, a1.w};
#pragma unroll
            for (int i = 0; i < 8; i++) {
                unsigned long long aa = pack2(am[i], am[i]);
#pragma unroll
                for (int j = 0; j < 4; j++) acc[i][j] = ffma2(aa, bb[j], acc[i][j]);
            }
        }
        if (hn) gemm_store_smem(As[cur ^ 1], Bs[cur ^ 1], tid, av, bv);
        __syncthreads();
    }

#pragma unroll
    for (int i = 0; i < 8; i++) {
        int m = m0 + ty * 8 + i;
#pragma unroll
        for (int j = 0; j < 4; j++) {
            float2 v = unpack2(acc[i][j]);
            int n = n0 + tx * 8 + j * 2;
            if (n     < N) C[(size_t)m * ldc + n]     = v.x;
            if (n + 1 < N) C[(size_t)m * ldc + n + 1] = v.y;
        }
    }
}

// ---------------- LSTM recurrent kernel ----------------
// grid (32, 2): block handles 4 batch rows of one LSTM, loops all 46 steps.
// z = xz[t] + h @ W_h ; per-gate LN (one warp per gate) ; cell LN ; outputs to g_o.
__global__ __launch_bounds__(128)
void lstm_kernel(const float* __restrict__ W1, const float* __restrict__ W2,
                 const float* __restrict__ lng1, const float* __restrict__ lnb1,
                 const float* __restrict__ lng2, const float* __restrict__ lnb2)
{
    int which = blockIdx.y;
    const float* Wh  = (which ? W2 : W1) + 300 * 512;   // rows 300..427
    const float* lng = which ? lng2 : lng1;
    const float* lnb = which ? lnb2 : lnb1;
    const float* xz  = g_xz[which];
    float* o_out     = g_o[which];

    int b0  = blockIdx.x * 4;
    int tid = threadIdx.x;
    int lane = tid & 31, warp = tid >> 5;

    __shared__ float hs[128][4];     // h transposed: [k][row]
    __shared__ float cs[4][128];
    __shared__ float zs[4][512];
    __shared__ float red[4][2][4];

#pragma unroll
    for (int r = 0; r < 4; r++) { hs[tid][r] = 0.f; cs[r][tid] = 0.f; }
    __syncthreads();

    int c0 = tid * 4;
    int gate = warp;            // warp g handles z-cols [128g, 128g+128)
    int jg = lane * 4;          // column within gate
    float gg[4], gb[4];
#pragma unroll
    for (int i = 0; i < 4; i++) {
        gg[i] = lng[gate * 128 + jg + i];
        gb[i] = lnb[gate * 128 + jg + i];
    }
    float g5 = lng[4 * 128 + tid], b5 = lnb[4 * 128 + tid];

    for (int t = 0; t < TT; t++) {
        // ---- z = xz[t] + h @ Wh  (thread owns cols c0..c0+3 for 4 rows) ----
        unsigned long long acc[4][2];
#pragma unroll
        for (int r = 0; r < 4; r++) {
            float4 x = *(const float4*)&xz[((size_t)(b0 + r) * TT + t) * 512 + c0];
            acc[r][0] = pack2(x.x, x.y);
            acc[r][1] = pack2(x.z, x.w);
        }
#pragma unroll 4
        for (int k = 0; k < 128; k++) {
            float4 w = *(const float4*)&Wh[(size_t)k * 512 + c0];
            unsigned long long w01 = pack2(w.x, w.y);
            unsigned long long w23 = pack2(w.z, w.w);
            float4 h4 = *(const float4*)&hs[k][0];
            unsigned long long h0 = pack2(h4.x, h4.x);
            unsigned long long h1 = pack2(h4.y, h4.y);
            unsigned long long h2 = pack2(h4.z, h4.z);
            unsigned long long h3 = pack2(h4.w, h4.w);
            acc[0][0] = ffma2(h0, w01, acc[0][0]); acc[0][1] = ffma2(h0, w23, acc[0][1]);
            acc[1][0] = ffma2(h1, w01, acc[1][0]); acc[1][1] = ffma2(h1, w23, acc[1][1]);
            acc[2][0] = ffma2(h2, w01, acc[2][0]); acc[2][1] = ffma2(h2, w23, acc[2][1]);
            acc[3][0] = ffma2(h3, w01, acc[3][0]); acc[3][1] = ffma2(h3, w23, acc[3][1]);
        }

        // ---- per-gate LayerNorm (warp = gate, 128 cols per gate) ----
#pragma unroll
        for (int r = 0; r < 4; r++) {
            float2 p0 = unpack2(acc[r][0]), p1 = unpack2(acc[r][1]);
            float v0 = p0.x, v1 = p0.y, v2 = p1.x, v3 = p1.y;
            float s  = v0 + v1 + v2 + v3;
            float ss = v0 * v0 + v1 * v1 + v2 * v2 + v3 * v3;
#pragma unroll
            for (int off = 16; off > 0; off >>= 1) {
                s  += __shfl_xor_sync(0xffffffffu, s,  off);
                ss += __shfl_xor_sync(0xffffffffu, ss, off);
            }
            float mu  = s * (1.f / 128.f);
            float var = ss * (1.f / 128.f) - mu * mu;
            float inv = rsqrtf(var + 1e-12f);
            zs[r][c0 + 0] = (v0 - mu) * inv * gg[0] + gb[0];
            zs[r][c0 + 1] = (v1 - mu) * inv * gg[1] + gb[1];
            zs[r][c0 + 2] = (v2 - mu) * inv * gg[2] + gb[2];
            zs[r][c0 + 3] = (v3 - mu) * inv * gg[3] + gb[3];
        }
        __syncthreads();

        // ---- cell update + cell LN + output (thread = h index j) ----
        int j = tid;
        float cn[4], og[4];
#pragma unroll
        for (int r = 0; r < 4; r++) {
            float ig = zs[r][j];
            float jj = zs[r][128 + j];
            float fg = zs[r][256 + j];
            og[r]    = zs[r][384 + j];
            float c_new = cs[r][j] * sigm(fg + 1.0f) + sigm(ig) * fmaxf(jj, 0.f);
            cs[r][j] = c_new;
            cn[r] = c_new;
            float s = c_new, ss = c_new * c_new;
#pragma unroll
            for (int off = 16; off > 0; off >>= 1) {
                s  += __shfl_xor_sync(0xffffffffu, s,  off);
                ss += __shfl_xor_sync(0xffffffffu, ss, off);
            }
            if (lane == 0) { red[r][0][warp] = s; red[r][1][warp] = ss; }
        }
        __syncthreads();

        float hout[4];
#pragma unroll
        for (int r = 0; r < 4; r++) {
            float S  = red[r][0][0] + red[r][0][1] + red[r][0][2] + red[r][0][3];
            float SS = red[r][1][0] + red[r][1][1] + red[r][1][2] + red[r][1][3];
            float mu  = S * (1.f / 128.f);
            float var = SS * (1.f / 128.f) - mu * mu;
            float hn = fmaxf((cn[r] - mu) * rsqrtf(var + 1e-12f) * g5 + b5, 0.f) * sigm(og[r]);
            hout[r] = hn;
            o_out[((size_t)(b0 + r) * TT + t) * 128 + j] = hn;
        }
        *(float4*)&hs[j][0] = make_float4(hout[0], hout[1], hout[2], hout[3]);
        __syncthreads();
    }
}

// ---------------- attention: softmax over time + dense(512, relu) ----------------
__global__ __launch_bounds__(128)
void attn_kernel(const float* __restrict__ v1, const float* __restrict__ Wo1, const float* __restrict__ bo1,
                 const float* __restrict__ v2, const float* __restrict__ Wo2, const float* __restrict__ bo2)
{
    int which = blockIdx.y, b = blockIdx.x;
    const float* v  = which ? v2  : v1;
    const float* Wo = which ? Wo2 : Wo1;
    const float* bo = which ? bo2 : bo1;
    const float* o  = g_o[which] + (size_t)b * TT * 128;
    float* a        = g_a[which] + (size_t)b * 512;

    int tid = threadIdx.x, lane = tid & 31, warp = tid >> 5;
    __shared__ float al[TT];
    __shared__ float ctxs[128];

    float4 vv = *(const float4*)&v[lane * 4];
    for (int t = warp; t < TT; t += 4) {
        float4 ov = *(const float4*)&o[t * 128 + lane * 4];
        float p = ov.x * vv.x + ov.y * vv.y + ov.z * vv.z + ov.w * vv.w;
#pragma unroll
        for (int off = 16; off > 0; off >>= 1) p += __shfl_xor_sync(0xffffffffu, p, off);
        if (lane == 0) al[t] = p;
    }
    __syncthreads();

    if (warp == 0) {
        float s0 = (lane < TT)      ? al[lane]      : -1e30f;
        float s1 = (lane + 32 < TT) ? al[lane + 32] : -1e30f;
        float m = fmaxf(s0, s1);
#pragma unroll
        for (int off = 16; off > 0; off >>= 1) m = fmaxf(m, __shfl_xor_sync(0xffffffffu, m, off));
        float e0 = (lane < TT)      ? expf(s0 - m) : 0.f;
        float e1 = (lane + 32 < TT) ? expf(s1 - m) : 0.f;
        float s = e0 + e1;
#pragma unroll
        for (int off = 16; off > 0; off >>= 1) s += __shfl_xor_sync(0xffffffffu, s, off);
        float inv = 1.f / s;
        if (lane < TT)      al[lane]      = e0 * inv;
        if (lane + 32 < TT) al[lane + 32] = e1 * inv;
    }
    __syncthreads();

    float cx = 0.f;
    for (int t = 0; t < TT; t++) cx += al[t] * o[t * 128 + tid];
    ctxs[tid] = cx;
    __syncthreads();

    int c0 = tid * 4;
    float4 accv = *(const float4*)&bo[c0];
#pragma unroll 4
    for (int k = 0; k < 128; k++) {
        float4 w = *(const float4*)&Wo[(size_t)k * 512 + c0];
        float x = ctxs[k];
        accv.x += x * w.x; accv.y += x * w.y; accv.z += x * w.z; accv.w += x * w.w;
    }
    a[c0 + 0] = fmaxf(accv.x, 0.f);
    a[c0 + 1] = fmaxf(accv.y, 0.f);
    a[c0 + 2] = fmaxf(accv.z, 0.f);
    a[c0 + 3] = fmaxf(accv.w, 0.f);
}

// ---------------- head: relu(concat @ W_h + b_h) @ W_out + b_out ----------------
__global__ __launch_bounds__(128)
void head_kernel(const float* __restrict__ Wh, const float* __restrict__ bh,
                 const float* __restrict__ Wout, const float* __restrict__ bout,
                 float* __restrict__ out)
{
    int b = blockIdx.x, tid = threadIdx.x;
    int lane = tid & 31, warp = tid >> 5;
    __shared__ float cat[1024];
    __shared__ float hid[512];
    __shared__ float red[2][4];

#pragma unroll
    for (int i = 0; i < 8; i++) {
        int k = tid + 128 * i;
        cat[k] = (k < 512) ? g_a[0][(size_t)b * 512 + k] : g_a[1][(size_t)b * 512 + k - 512];
    }
    __syncthreads();

    int c0 = tid * 4;
    float4 acc = *(const float4*)&bh[c0];
#pragma unroll 4
    for (int k = 0; k < 1024; k++) {
        float4 w = *(const float4*)&Wh[(size_t)k * 512 + c0];
        float x = cat[k];
        acc.x += x * w.x; acc.y += x * w.y; acc.z += x * w.z; acc.w += x * w.w;
    }
    hid[c0 + 0] = fmaxf(acc.x, 0.f);
    hid[c0 + 1] = fmaxf(acc.y, 0.f);
    hid[c0 + 2] = fmaxf(acc.z, 0.f);
    hid[c0 + 3] = fmaxf(acc.w, 0.f);
    __syncthreads();

    float p0 = 0.f, p1 = 0.f;
#pragma unroll
    for (int i = 0; i < 4; i++) {
        float h = hid[c0 + i];
        p0 += h * Wout[(c0 + i) * 2 + 0];
        p1 += h * Wout[(c0 + i) * 2 + 1];
    }
#pragma unroll
    for (int off = 16; off > 0; off >>= 1) {
        p0 += __shfl_xor_sync(0xffffffffu, p0, off);
        p1 += __shfl_xor_sync(0xffffffffu, p1, off);
    }
    if (lane == 0) { red[0][warp] = p0; red[1][warp] = p1; }
    __syncthreads();
    if (tid == 0) {
        out[b * 2 + 0] = red[0][0] + red[0][1] + red[0][2] + red[0][3] + bout[0];
        out[b * 2 + 1] = red[1][0] + red[1][1] + red[1][2] + red[1][3] + bout[1];
    }
}

// ---------------- launch ----------------
extern "C" void kernel_launch(void* const* d_in, const int* in_sizes, int n_in,
                              void* d_out, int out_size)
{
    const float* x1     = (const float*)d_in[0];
    const float* x2     = (const float*)d_in[1];
    const float* embed1 = (const float*)d_in[2];
    const float* embed2 = (const float*)d_in[3];
    const float* Wl1    = (const float*)d_in[4];
    const float* Wl2    = (const float*)d_in[5];
    const float* lng1   = (const float*)d_in[6];
    const float* lnb1   = (const float*)d_in[7];
    const float* lng2   = (const float*)d_in[8];
    const float* lnb2   = (const float*)d_in[9];
    const float* av1    = (const float*)d_in[10];
    const float* aWo1   = (const float*)d_in[11];
    const float* abo1   = (const float*)d_in[12];
    const float* av2    = (const float*)d_in[13];
    const float* aWo2   = (const float*)d_in[14];
    const float* abo2   = (const float*)d_in[15];
    const float* Wh     = (const float*)d_in[16];
    const float* bh     = (const float*)d_in[17];
    const float* Wout   = (const float*)d_in[18];
    const float* bout   = (const float*)d_in[19];
    float* out = (float*)d_out;

    // 1) e = x @ embed         [5888,8150]@[8150,300]
    gemm_kernel<<<dim3(3, 46, 2), 256>>>(x1, x2, embed1, embed2,
                                         MROWS, EE, VV, VV, EE, EE, 0);
    // 2) xz = e @ W_lstm[0:300,:]  [5888,300]@[300,512]
    gemm_kernel<<<dim3(4, 46, 2), 256>>>(x1, x2, Wl1, Wl2,
                                         MROWS, 512, EE, EE, 512, 512, 1);
    // 3) recurrence (persistent per-batch-group blocks)
    lstm_kernel<<<dim3(32, 2), 128>>>(Wl1, Wl2, lng1, lnb1, lng2, lnb2);
    // 4) attention
    attn_kernel<<<dim3(128, 2), 128>>>(av1, aWo1, abo1, av2, aWo2, abo2);
    // 5) head
    head_kernel<<<128, 128>>>(Wh, bh, Wout, bout, out);
}

// round 7
// speedup vs baseline: 1.5728x; 1.5728x over previous
#include <cuda_runtime.h>
#include <math.h>

// ---------------- scratch (static device memory; no allocations) ----------------
#define BB 128
#define TT 46
#define VV 8150
#define EE 300
#define HH 128
#define MROWS (BB*TT)   // 5888

__device__ float g_e [2][MROWS*EE];    // embeddings output [5888,300]
__device__ float g_xz[2][MROWS*512];   // x-part of gates   [5888,512]
__device__ float g_o [2][MROWS*HH];    // lstm outputs      [b*46+t,128]
__device__ float g_a [2][BB*512];      // attention outputs [128,512]

// ---------------- f32x2 helpers ----------------
__device__ __forceinline__ unsigned long long ffma2(unsigned long long a,
                                                    unsigned long long b,
                                                    unsigned long long c) {
    unsigned long long d;
    asm("fma.rn.f32x2 %0, %1, %2, %3;" : "=l"(d) : "l"(a), "l"(b), "l"(c));
    return d;
}
__device__ __forceinline__ unsigned long long pack2(float x, float y) {
    unsigned long long d;
    asm("mov.b64 %0, {%1, %2};" : "=l"(d) : "r"(__float_as_uint(x)), "r"(__float_as_uint(y)));
    return d;
}
__device__ __forceinline__ float2 unpack2(unsigned long long v) {
    unsigned int lo, hi;
    asm("mov.b64 {%0, %1}, %2;" : "=r"(lo), "=r"(hi) : "l"(v));
    return make_float2(__uint_as_float(lo), __uint_as_float(hi));
}
__device__ __forceinline__ float sigm(float x) { return 1.0f / (1.0f + expf(-x)); }

// ---------------- fp32 GEMM: C = A @ B ----------------
// BM=128, BN=128, BK=8, 256 threads, 8x8 per thread, f32x2 accumulators.
// A stored DUPLICATED in smem (each value twice, adjacent) so the A fragment
// is loaded as ulonglong2 directly (no packing movs). B fragment read at
// cols tx*4 and 64+tx*4 -> conflict-free LDS.128 whose 64-bit halves are the
// f32x2 operands directly.
// mode 0: A = x{1,2} (ext), B = embed{1,2} (ext), C = g_e[z]
// mode 1: A = g_e[z],       B = W_lstm{1,2} rows 0..K-1, C = g_xz[z]

#define APAD 264   // 256 used + 8 pad

__device__ __forceinline__ void gemm_load_regs(
    const float* __restrict__ A, const float* __restrict__ Bm,
    int N, int K, int lda, int ldb,
    int m0, int n0, int k0, int tid, float2 av[2], float4& bv)
{
#pragma unroll
    for (int j = 0; j < 2; j++) {
        int l  = tid + 256 * j;
        int am = l >> 2;
        int ak = (l & 3) * 2;
        int k  = k0 + ak;
        float2 v = make_float2(0.f, 0.f);
        const float* p = A + (size_t)(m0 + am) * lda + k;
        if (k + 1 < K)      v = *(const float2*)p;
        else if (k < K)     v.x = *p;
        av[j] = v;
    }
    int bk = tid >> 5, bn = (tid & 31) * 4;
    int k = k0 + bk, n = n0 + bn;
    float4 v = make_float4(0.f, 0.f, 0.f, 0.f);
    if (k < K) {
        const float* p = Bm + (size_t)k * ldb + n;
        if (n + 3 < N) v = *(const float4*)p;
        else {
            if (n     < N) v.x = p[0];
            if (n + 1 < N) v.y = p[1];
            if (n + 2 < N) v.z = p[2];
        }
    }
    bv = v;
}

__device__ __forceinline__ void gemm_store_smem(
    float (*As)[APAD], float (*Bs)[128], int tid, const float2 av[2], const float4& bv)
{
#pragma unroll
    for (int j = 0; j < 2; j++) {
        int l  = tid + 256 * j;
        int am = l >> 2;
        int ak = (l & 3) * 2;
        // duplicated store: value appears at [2m] and [2m+1]
        *(float2*)&As[ak][2 * am]     = make_float2(av[j].x, av[j].x);
        *(float2*)&As[ak + 1][2 * am] = make_float2(av[j].y, av[j].y);
    }
    int bk = tid >> 5, bn = (tid & 31) * 4;
    *(float4*)&Bs[bk][bn] = bv;
}

__global__ __launch_bounds__(256, 2)
void gemm_kernel(const float* __restrict__ Aext0, const float* __restrict__ Aext1,
                 const float* __restrict__ Bv0,  const float* __restrict__ Bv1,
                 int M, int N, int K, int lda, int ldb, int ldc, int mode)
{
    int z = blockIdx.z;
    const float* A  = (mode == 0) ? (z ? Aext1 : Aext0) : g_e[z];
    const float* Bm = z ? Bv1 : Bv0;
    float* C = (mode == 0) ? g_e[z] : g_xz[z];

    __shared__ __align__(16) float As[2][8][APAD];
    __shared__ __align__(16) float Bs[2][8][128];

    int tid = threadIdx.x;
    int tx = tid & 15, ty = tid >> 4;
    int m0 = blockIdx.y * 128;
    int n0 = blockIdx.x * 128;

    unsigned long long acc[8][4];
#pragma unroll
    for (int i = 0; i < 8; i++)
#pragma unroll
        for (int j = 0; j < 4; j++) acc[i][j] = 0ULL;

    int numK = (K + 7) / 8;

    float2 av[2]; float4 bv;
    gemm_load_regs(A, Bm, N, K, lda, ldb, m0, n0, 0, tid, av, bv);
    gemm_store_smem(As[0], Bs[0], tid, av, bv);
    __syncthreads();

    for (int kt = 0; kt < numK; kt++) {
        int cur = kt & 1;
        bool hn = (kt + 1) < numK;
        if (hn) gemm_load_regs(A, Bm, N, K, lda, ldb, m0, n0, (kt + 1) * 8, tid, av, bv);

#pragma unroll
        for (int kk = 0; kk < 8; kk++) {
            const float* ar = &As[cur][kk][16 * ty];
            ulonglong2 a01 = *(const ulonglong2*)(ar);
            ulonglong2 a23 = *(const ulonglong2*)(ar + 4);
            ulonglong2 a45 = *(const ulonglong2*)(ar + 8);
            ulonglong2 a67 = *(const ulonglong2*)(ar + 12);
            ulonglong2 b01 = *(const ulonglong2*)&Bs[cur][kk][tx * 4];
            ulonglong2 b23 = *(const ulonglong2*)&Bs[cur][kk][64 + tx * 4];
            unsigned long long ad[8] = {a01.x, a01.y, a23.x, a23.y,
                                        a45.x, a45.y, a67.x, a67.y};
#pragma unroll
            for (int i = 0; i < 8; i++) {
                acc[i][0] = ffma2(ad[i], b01.x, acc[i][0]);
                acc[i][1] = ffma2(ad[i], b01.y, acc[i][1]);
                acc[i][2] = ffma2(ad[i], b23.x, acc[i][2]);
                acc[i][3] = ffma2(ad[i], b23.y, acc[i][3]);
            }
        }
        if (hn) gemm_store_smem(As[cur ^ 1], Bs[cur ^ 1], tid, av, bv);
        __syncthreads();
    }

    // store: cols n0 + tx*4 + {0..3}  and  n0 + 64 + tx*4 + {0..3}
#pragma unroll
    for (int i = 0; i < 8; i++) {
        int m = m0 + ty * 8 + i;
        float* crow = C + (size_t)m * ldc;
        float2 v0 = unpack2(acc[i][0]);
        float2 v1 = unpack2(acc[i][1]);
        float2 v2 = unpack2(acc[i][2]);
        float2 v3 = unpack2(acc[i][3]);
        int na = n0 + tx * 4;
        if (na + 3 < N) {
            *(float4*)&crow[na] = make_float4(v0.x, v0.y, v1.x, v1.y);
        } else {
            if (na     < N) crow[na]     = v0.x;
            if (na + 1 < N) crow[na + 1] = v0.y;
            if (na + 2 < N) crow[na + 2] = v1.x;
            if (na + 3 < N) crow[na + 3] = v1.y;
        }
        int nb = n0 + 64 + tx * 4;
        if (nb + 3 < N) {
            *(float4*)&crow[nb] = make_float4(v2.x, v2.y, v3.x, v3.y);
        } else {
            if (nb     < N) crow[nb]     = v2.x;
            if (nb + 1 < N) crow[nb + 1] = v2.y;
            if (nb + 2 < N) crow[nb + 2] = v3.x;
            if (nb + 3 < N) crow[nb + 3] = v3.y;
        }
    }
}

// ---------------- LSTM recurrent kernel ----------------
// grid (32, 2): block handles 4 batch rows of one LSTM, loops all 46 steps.
__global__ __launch_bounds__(128)
void lstm_kernel(const float* __restrict__ W1, const float* __restrict__ W2,
                 const float* __restrict__ lng1, const float* __restrict__ lnb1,
                 const float* __restrict__ lng2, const float* __restrict__ lnb2)
{
    int which = blockIdx.y;
    const float* Wh  = (which ? W2 : W1) + 300 * 512;   // rows 300..427
    const float* lng = which ? lng2 : lng1;
    const float* lnb = which ? lnb2 : lnb1;
    const float* xz  = g_xz[which];
    float* o_out     = g_o[which];

    int b0  = blockIdx.x * 4;
    int tid = threadIdx.x;
    int lane = tid & 31, warp = tid >> 5;

    __shared__ float hs[128][4];     // h transposed: [k][row]
    __shared__ float cs[4][128];
    __shared__ float zs[4][512];
    __shared__ float red[4][2][4];

#pragma unroll
    for (int r = 0; r < 4; r++) { hs[tid][r] = 0.f; cs[r][tid] = 0.f; }
    __syncthreads();

    int c0 = tid * 4;
    int gate = warp;
    int jg = lane * 4;
    float gg[4], gb[4];
#pragma unroll
    for (int i = 0; i < 4; i++) {
        gg[i] = lng[gate * 128 + jg + i];
        gb[i] = lnb[gate * 128 + jg + i];
    }
    float g5 = lng[4 * 128 + tid], b5 = lnb[4 * 128 + tid];

    for (int t = 0; t < TT; t++) {
        unsigned long long acc[4][2];
#pragma unroll
        for (int r = 0; r < 4; r++) {
            float4 x = *(const float4*)&xz[((size_t)(b0 + r) * TT + t) * 512 + c0];
            acc[r][0] = pack2(x.x, x.y);
            acc[r][1] = pack2(x.z, x.w);
        }
#pragma unroll 4
        for (int k = 0; k < 128; k++) {
            float4 w = *(const float4*)&Wh[(size_t)k * 512 + c0];
            unsigned long long w01 = pack2(w.x, w.y);
            unsigned long long w23 = pack2(w.z, w.w);
            float4 h4 = *(const float4*)&hs[k][0];
            unsigned long long h0 = pack2(h4.x, h4.x);
            unsigned long long h1 = pack2(h4.y, h4.y);
            unsigned long long h2 = pack2(h4.z, h4.z);
            unsigned long long h3 = pack2(h4.w, h4.w);
            acc[0][0] = ffma2(h0, w01, acc[0][0]); acc[0][1] = ffma2(h0, w23, acc[0][1]);
            acc[1][0] = ffma2(h1, w01, acc[1][0]); acc[1][1] = ffma2(h1, w23, acc[1][1]);
            acc[2][0] = ffma2(h2, w01, acc[2][0]); acc[2][1] = ffma2(h2, w23, acc[2][1]);
            acc[3][0] = ffma2(h3, w01, acc[3][0]); acc[3][1] = ffma2(h3, w23, acc[3][1]);
        }

#pragma unroll
        for (int r = 0; r < 4; r++) {
            float2 p0 = unpack2(acc[r][0]), p1 = unpack2(acc[r][1]);
            float v0 = p0.x, v1 = p0.y, v2 = p1.x, v3 = p1.y;
            float s  = v0 + v1 + v2 + v3;
            float ss = v0 * v0 + v1 * v1 + v2 * v2 + v3 * v3;
#pragma unroll
            for (int off = 16; off > 0; off >>= 1) {
                s  += __shfl_xor_sync(0xffffffffu, s,  off);
                ss += __shfl_xor_sync(0xffffffffu, ss, off);
            }
            float mu  = s * (1.f / 128.f);
            float var = ss * (1.f / 128.f) - mu * mu;
            float inv = rsqrtf(var + 1e-12f);
            zs[r][c0 + 0] = (v0 - mu) * inv * gg[0] + gb[0];
            zs[r][c0 + 1] = (v1 - mu) * inv * gg[1] + gb[1];
            zs[r][c0 + 2] = (v2 - mu) * inv * gg[2] + gb[2];
            zs[r][c0 + 3] = (v3 - mu) * inv * gg[3] + gb[3];
        }
        __syncthreads();

        int j = tid;
        float cn[4], og[4];
#pragma unroll
        for (int r = 0; r < 4; r++) {
            float ig = zs[r][j];
            float jj = zs[r][128 + j];
            float fg = zs[r][256 + j];
            og[r]    = zs[r][384 + j];
            float c_new = cs[r][j] * sigm(fg + 1.0f) + sigm(ig) * fmaxf(jj, 0.f);
            cs[r][j] = c_new;
            cn[r] = c_new;
            float s = c_new, ss = c_new * c_new;
#pragma unroll
            for (int off = 16; off > 0; off >>= 1) {
                s  += __shfl_xor_sync(0xffffffffu, s,  off);
                ss += __shfl_xor_sync(0xffffffffu, ss, off);
            }
            if (lane == 0) { red[r][0][warp] = s; red[r][1][warp] = ss; }
        }
        __syncthreads();

        float hout[4];
#pragma unroll
        for (int r = 0; r < 4; r++) {
            float S  = red[r][0][0] + red[r][0][1] + red[r][0][2] + red[r][0][3];
            float SS = red[r][1][0] + red[r][1][1] + red[r][1][2] + red[r][1][3];
            float mu  = S * (1.f / 128.f);
            float var = SS * (1.f / 128.f) - mu * mu;
            float hn = fmaxf((cn[r] - mu) * rsqrtf(var + 1e-12f) * g5 + b5, 0.f) * sigm(og[r]);
            hout[r] = hn;
            o_out[((size_t)(b0 + r) * TT + t) * 128 + j] = hn;
        }
        *(float4*)&hs[j][0] = make_float4(hout[0], hout[1], hout[2], hout[3]);
        __syncthreads();
    }
}

// ---------------- attention: softmax over time + dense(512, relu) ----------------
__global__ __launch_bounds__(128)
void attn_kernel(const float* __restrict__ v1, const float* __restrict__ Wo1, const float* __restrict__ bo1,
                 const float* __restrict__ v2, const float* __restrict__ Wo2, const float* __restrict__ bo2)
{
    int which = blockIdx.y, b = blockIdx.x;
    const float* v  = which ? v2  : v1;
    const float* Wo = which ? Wo2 : Wo1;
    const float* bo = which ? bo2 : bo1;
    const float* o  = g_o[which] + (size_t)b * TT * 128;
    float* a        = g_a[which] + (size_t)b * 512;

    int tid = threadIdx.x, lane = tid & 31, warp = tid >> 5;
    __shared__ float al[TT];
    __shared__ float ctxs[128];

    float4 vv = *(const float4*)&v[lane * 4];
    for (int t = warp; t < TT; t += 4) {
        float4 ov = *(const float4*)&o[t * 128 + lane * 4];
        float p = ov.x * vv.x + ov.y * vv.y + ov.z * vv.z + ov.w * vv.w;
#pragma unroll
        for (int off = 16; off > 0; off >>= 1) p += __shfl_xor_sync(0xffffffffu, p, off);
        if (lane == 0) al[t] = p;
    }
    __syncthreads();

    if (warp == 0) {
        float s0 = (lane < TT)      ? al[lane]      : -1e30f;
        float s1 = (lane + 32 < TT) ? al[lane + 32] : -1e30f;
        float m = fmaxf(s0, s1);
#pragma unroll
        for (int off = 16; off > 0; off >>= 1) m = fmaxf(m, __shfl_xor_sync(0xffffffffu, m, off));
        float e0 = (lane < TT)      ? expf(s0 - m) : 0.f;
        float e1 = (lane + 32 < TT) ? expf(s1 - m) : 0.f;
        float s = e0 + e1;
#pragma unroll
        for (int off = 16; off > 0; off >>= 1) s += __shfl_xor_sync(0xffffffffu, s, off);
        float inv = 1.f / s;
        if (lane < TT)      al[lane]      = e0 * inv;
        if (lane + 32 < TT) al[lane + 32] = e1 * inv;
    }
    __syncthreads();

    float cx = 0.f;
    for (int t = 0; t < TT; t++) cx += al[t] * o[t * 128 + tid];
    ctxs[tid] = cx;
    __syncthreads();

    int c0 = tid * 4;
    float4 accv = *(const float4*)&bo[c0];
#pragma unroll 4
    for (int k = 0; k < 128; k++) {
        float4 w = *(const float4*)&Wo[(size_t)k * 512 + c0];
        float x = ctxs[k];
        accv.x += x * w.x; accv.y += x * w.y; accv.z += x * w.z; accv.w += x * w.w;
    }
    a[c0 + 0] = fmaxf(accv.x, 0.f);
    a[c0 + 1] = fmaxf(accv.y, 0.f);
    a[c0 + 2] = fmaxf(accv.z, 0.f);
    a[c0 + 3] = fmaxf(accv.w, 0.f);
}

// ---------------- head: relu(concat @ W_h + b_h) @ W_out + b_out ----------------
__global__ __launch_bounds__(128)
void head_kernel(const float* __restrict__ Wh, const float* __restrict__ bh,
                 const float* __restrict__ Wout, const float* __restrict__ bout,
                 float* __restrict__ out)
{
    int b = blockIdx.x, tid = threadIdx.x;
    int lane = tid & 31, warp = tid >> 5;
    __shared__ float cat[1024];
    __shared__ float hid[512];
    __shared__ float red[2][4];

#pragma unroll
    for (int i = 0; i < 8; i++) {
        int k = tid + 128 * i;
        cat[k] = (k < 512) ? g_a[0][(size_t)b * 512 + k] : g_a[1][(size_t)b * 512 + k - 512];
    }
    __syncthreads();

    int c0 = tid * 4;
    float4 acc = *(const float4*)&bh[c0];
#pragma unroll 4
    for (int k = 0; k < 1024; k++) {
        float4 w = *(const float4*)&Wh[(size_t)k * 512 + c0];
        float x = cat[k];
        acc.x += x * w.x; acc.y += x * w.y; acc.z += x * w.z; acc.w += x * w.w;
    }
    hid[c0 + 0] = fmaxf(acc.x, 0.f);
    hid[c0 + 1] = fmaxf(acc.y, 0.f);
    hid[c0 + 2] = fmaxf(acc.z, 0.f);
    hid[c0 + 3] = fmaxf(acc.w, 0.f);
    __syncthreads();

    float p0 = 0.f, p1 = 0.f;
#pragma unroll
    for (int i = 0; i < 4; i++) {
        float h = hid[c0 + i];
        p0 += h * Wout[(c0 + i) * 2 + 0];
        p1 += h * Wout[(c0 + i) * 2 + 1];
    }
#pragma unroll
    for (int off = 16; off > 0; off >>= 1) {
        p0 += __shfl_xor_sync(0xffffffffu, p0, off);
        p1 += __shfl_xor_sync(0xffffffffu, p1, off);
    }
    if (lane == 0) { red[0][warp] = p0; red[1][warp] = p1; }
    __syncthreads();
    if (tid == 0) {
        out[b * 2 + 0] = red[0][0] + red[0][1] + red[0][2] + red[0][3] + bout[0];
        out[b * 2 + 1] = red[1][0] + red[1][1] + red[1][2] + red[1][3] + bout[1];
    }
}

// ---------------- launch ----------------
extern "C" void kernel_launch(void* const* d_in, const int* in_sizes, int n_in,
                              void* d_out, int out_size)
{
    const float* x1     = (const float*)d_in[0];
    const float* x2     = (const float*)d_in[1];
    const float* embed1 = (const float*)d_in[2];
    const float* embed2 = (const float*)d_in[3];
    const float* Wl1    = (const float*)d_in[4];
    const float* Wl2    = (const float*)d_in[5];
    const float* lng1   = (const float*)d_in[6];
    const float* lnb1   = (const float*)d_in[7];
    const float* lng2   = (const float*)d_in[8];
    const float* lnb2   = (const float*)d_in[9];
    const float* av1    = (const float*)d_in[10];
    const float* aWo1   = (const float*)d_in[11];
    const float* abo1   = (const float*)d_in[12];
    const float* av2    = (const float*)d_in[13];
    const float* aWo2   = (const float*)d_in[14];
    const float* abo2   = (const float*)d_in[15];
    const float* Wh     = (const float*)d_in[16];
    const float* bh     = (const float*)d_in[17];
    const float* Wout   = (const float*)d_in[18];
    const float* bout   = (const float*)d_in[19];
    float* out = (float*)d_out;

    // 1) e = x @ embed         [5888,8150]@[8150,300]
    gemm_kernel<<<dim3(3, 46, 2), 256>>>(x1, x2, embed1, embed2,
                                         MROWS, EE, VV, VV, EE, EE, 0);
    // 2) xz = e @ W_lstm[0:300,:]  [5888,300]@[300,512]
    gemm_kernel<<<dim3(4, 46, 2), 256>>>(x1, x2, Wl1, Wl2,
                                         MROWS, 512, EE, EE, 512, 512, 1);
    // 3) recurrence (persistent per-batch-group blocks)
    lstm_kernel<<<dim3(32, 2), 128>>>(Wl1, Wl2, lng1, lnb1, lng2, lnb2);
    // 4) attention
    attn_kernel<<<dim3(128, 2), 128>>>(av1, aWo1, abo1, av2, aWo2, abo2);
    // 5) head
    head_kernel<<<128, 128>>>(Wh, bh, Wout, bout, out);
}

// round 10
// speedup vs baseline: 2.6388x; 1.6778x over previous
#include <cuda_runtime.h>
#include <cuda.h>
#include <cuda_bf16.h>
#include <math.h>
#include <stdint.h>

// ---------------- scratch (static device memory; no allocations) ----------------
#define BB 128
#define TT 46
#define VV 8150
#define EE 300
#define HH 128
#define MROWS (BB*TT)   // 5888
#define KPAD 8192
#define NPAD 384

__device__ float g_ep[2][2][MROWS*EE];   // split-K partial embeddings [z][kz][5888,300]
__device__ float g_xz[2][MROWS*512];     // x-part of gates
__device__ float g_o [2][MROWS*HH];      // lstm outputs
__device__ float g_a [2][BB*512];        // attention outputs

// bf16 split operands
__device__ __nv_bfloat16 g_xhi[2][(size_t)MROWS*KPAD];
__device__ __nv_bfloat16 g_xlo[2][(size_t)MROWS*KPAD];
__device__ __nv_bfloat16 g_ehT[2][(size_t)NPAD*KPAD];
__device__ __nv_bfloat16 g_elT[2][(size_t)NPAD*KPAD];

// ---------------- helpers ----------------
__device__ __forceinline__ unsigned long long ffma2(unsigned long long a,
                                                    unsigned long long b,
                                                    unsigned long long c) {
    unsigned long long d;
    asm("fma.rn.f32x2 %0, %1, %2, %3;" : "=l"(d) : "l"(a), "l"(b), "l"(c));
    return d;
}
__device__ __forceinline__ unsigned long long pack2(float x, float y) {
    unsigned long long d;
    asm("mov.b64 %0, {%1, %2};" : "=l"(d) : "r"(__float_as_uint(x)), "r"(__float_as_uint(y)));
    return d;
}
__device__ __forceinline__ float2 unpack2(unsigned long long v) {
    unsigned int lo, hi;
    asm("mov.b64 {%0, %1}, %2;" : "=r"(lo), "=r"(hi) : "l"(v));
    return make_float2(__uint_as_float(lo), __uint_as_float(hi));
}
__device__ __forceinline__ float sigm(float x) { return 1.0f / (1.0f + expf(-x)); }

__device__ __forceinline__ uint32_t smem_u32(const void* p) {
    uint32_t a;
    asm("{ .reg .u64 t; cvta.to.shared.u64 t, %1; cvt.u32.u64 %0, t; }" : "=r"(a) : "l"(p));
    return a;
}

#define MBAR_INIT(a, cnt) asm volatile("mbarrier.init.shared.b64 [%0], %1;" :: "r"(a), "r"(cnt) : "memory")
#define MBAR_EXPECT_TX(a, b) asm volatile("mbarrier.arrive.expect_tx.shared.b64 _, [%0], %1;" :: "r"(a), "r"(b) : "memory")
#define MBAR_WAIT(a, ph) do { \
    uint32_t _m = (a), _p = (ph), _d; \
    asm volatile("{ .reg .pred p; mbarrier.try_wait.parity.acquire.cta.shared::cta.b64 p, [%1], %2; selp.b32 %0,1,0,p; }" \
        : "=r"(_d) : "r"(_m), "r"(_p) : "memory"); \
    if (!_d) { \
        asm volatile("{ .reg .pred P1; WL_%=: mbarrier.try_wait.parity.acquire.cta.shared::cta.b64 P1, [%0], %1, 0x989680; @P1 bra.uni WD_%=; bra.uni WL_%=; WD_%=: }" \
            :: "r"(_m), "r"(_p) : "memory"); \
    } } while (0)

__device__ __forceinline__ void tma2d(uint32_t smem, const CUtensorMap* m,
                                      int x, int y, uint32_t mbar) {
    asm volatile(
        "cp.async.bulk.tensor.2d.shared::cta.global.tile.mbarrier::complete_tx::bytes "
        "[%0], [%1, {%2, %3}], [%4];"
        :: "r"(smem), "l"(m), "r"(x), "r"(y), "r"(mbar) : "memory");
}

__device__ __forceinline__ void ldsm4(uint32_t* r, uint32_t a) {
    asm volatile("ldmatrix.sync.aligned.m8n8.x4.shared.b16 {%0,%1,%2,%3}, [%4];"
        : "=r"(r[0]), "=r"(r[1]), "=r"(r[2]), "=r"(r[3]) : "r"(a));
}
__device__ __forceinline__ void ldsm2(uint32_t* r, uint32_t a) {
    asm volatile("ldmatrix.sync.aligned.m8n8.x2.shared.b16 {%0,%1}, [%2];"
        : "=r"(r[0]), "=r"(r[1]) : "r"(a));
}
__device__ __forceinline__ void mma16816(float* d, const uint32_t* a, const uint32_t* b) {
    asm volatile("mma.sync.aligned.m16n8k16.row.col.f32.bf16.bf16.f32 "
        "{%0,%1,%2,%3}, {%4,%5,%6,%7}, {%8,%9}, {%0,%1,%2,%3};"
        : "+f"(d[0]), "+f"(d[1]), "+f"(d[2]), "+f"(d[3])
        : "r"(a[0]), "r"(a[1]), "r"(a[2]), "r"(a[3]), "r"(b[0]), "r"(b[1]));
}

// ---------------- conversion kernels ----------------
__global__ __launch_bounds__(256)
void convx_kernel(const float* __restrict__ x, int z)
{
    size_t idx = (size_t)blockIdx.x * 256 + threadIdx.x;
    int row = (int)(idx >> 10);
    int kk  = (int)(idx & 1023) << 3;
    __align__(16) __nv_bfloat16 h[8], l[8];
#pragma unroll
    for (int j = 0; j < 8; j++) {
        int k = kk + j;
        float v = (k < VV) ? x[(size_t)row * VV + k] : 0.f;
        __nv_bfloat16 hb = __float2bfloat16(v);
        h[j] = hb;
        l[j] = __float2bfloat16(v - __bfloat162float(hb));
    }
    size_t o = (size_t)row * KPAD + kk;
    *(uint4*)&g_xhi[z][o] = *(uint4*)h;
    *(uint4*)&g_xlo[z][o] = *(uint4*)l;
}

__global__ __launch_bounds__(256)
void convE_kernel(const float* __restrict__ embed, int z)
{
    size_t idx = (size_t)blockIdx.x * 256 + threadIdx.x;
    int n  = (int)(idx >> 10);
    int kk = (int)(idx & 1023) << 3;
    __align__(16) __nv_bfloat16 h[8], l[8];
#pragma unroll
    for (int j = 0; j < 8; j++) {
        int k = kk + j;
        float v = (n < EE && k < VV) ? embed[(size_t)k * EE + n] : 0.f;
        __nv_bfloat16 hb = __float2bfloat16(v);
        h[j] = hb;
        l[j] = __float2bfloat16(v - __bfloat162float(hb));
    }
    size_t o = (size_t)n * KPAD + kk;
    *(uint4*)&g_ehT[z][o] = *(uint4*)h;
    *(uint4*)&g_elT[z][o] = *(uint4*)l;
}

// ---------------- HMMA bf16-split GEMM with TMA ----------------
// CTA: M=128, N=320, K=4096 (split-K 2). Kc=64 bf16 per chunk.
// Stage: Ahi 16K | Alo 16K | Bhi 40K | Blo 40K = 112K. 2 stages.
// 256 threads, 8 warps as 2(M)x4(N); warp tile 64x80.
#define STG_B   114688
#define SMEM_H  (2*STG_B + 64)
#define NCHUNK  64

__device__ __forceinline__ void hmma_issue(uint32_t sb, int s, int k0, int m0,
    const CUtensorMap* pAh, const CUtensorMap* pAl,
    const CUtensorMap* pBh, const CUtensorMap* pBl)
{
    uint32_t mb = sb + 2*STG_B + 8*s;
    uint32_t base = sb + s*STG_B;
    MBAR_EXPECT_TX(mb, STG_B);
    tma2d(base,                 pAh, k0, m0,  mb);
    tma2d(base + 16384,         pAl, k0, m0,  mb);
    tma2d(base + 32768,         pBh, k0, 0,   mb);
    tma2d(base + 32768 + 20480, pBh, k0, 160, mb);
    tma2d(base + 73728,         pBl, k0, 0,   mb);
    tma2d(base + 73728 + 20480, pBl, k0, 160, mb);
}

__global__ __launch_bounds__(256, 1)
void hmma_kernel(int z,
    const __grid_constant__ CUtensorMap mAh0, const __grid_constant__ CUtensorMap mAl0,
    const __grid_constant__ CUtensorMap mBh0, const __grid_constant__ CUtensorMap mBl0,
    const __grid_constant__ CUtensorMap mAh1, const __grid_constant__ CUtensorMap mAl1,
    const __grid_constant__ CUtensorMap mBh1, const __grid_constant__ CUtensorMap mBl1)
{
    extern __shared__ __align__(1024) char smem[];
    uint32_t sb = smem_u32(smem);
    int tid = threadIdx.x, lane = tid & 31, wid = tid >> 5;
    int kz = blockIdx.x, m0 = blockIdx.y * 128;
    int wm = wid & 1, wn = wid >> 1;

    const CUtensorMap* pAh = z ? &mAh1 : &mAh0;
    const CUtensorMap* pAl = z ? &mAl1 : &mAl0;
    const CUtensorMap* pBh = z ? &mBh1 : &mBh0;
    const CUtensorMap* pBl = z ? &mBl1 : &mBl0;

    if (tid == 0) { MBAR_INIT(sb + 2*STG_B, 1); MBAR_INIT(sb + 2*STG_B + 8, 1); }
    __syncthreads();

    int kbase = kz * 4096;
    if (tid == 0) {
        hmma_issue(sb, 0, kbase,      m0, pAh, pAl, pBh, pBl);
        hmma_issue(sb, 1, kbase + 64, m0, pAh, pAl, pBh, pBl);
    }

    // per-thread ldmatrix offsets
    int u0 = lane >> 4;              // A: k half (16B unit)
    int u1 = (lane >> 3) & 1;        // B: k half
    int aoff[4], axr[4];
#pragma unroll
    for (int mf = 0; mf < 4; mf++) {
        int mr = wm * 64 + mf * 16 + (lane & 15);
        aoff[mf] = mr * 128;
        axr[mf]  = mr & 7;
    }
    int noff[10], nxr[10];
#pragma unroll
    for (int nf = 0; nf < 10; nf++) {
        int nr = wn * 80 + nf * 8 + (lane & 7);
        noff[nf] = nr * 128;
        nxr[nf]  = nr & 7;
    }

    float acc[4][10][4];
#pragma unroll
    for (int mf = 0; mf < 4; mf++)
#pragma unroll
        for (int nf = 0; nf < 10; nf++)
#pragma unroll
            for (int q = 0; q < 4; q++) acc[mf][nf][q] = 0.f;

    int ph0 = 0, ph1 = 0;
    for (int c = 0; c < NCHUNK; c++) {
        int s = c & 1;
        if (s == 0) { MBAR_WAIT(sb + 2*STG_B, ph0); ph0 ^= 1; }
        else        { MBAR_WAIT(sb + 2*STG_B + 8, ph1); ph1 ^= 1; }
        uint32_t base = sb + s * STG_B;

#pragma unroll
        for (int ks = 0; ks < 4; ks++) {
            uint32_t a[4][4], bh[10][2], bl[10][2];
#pragma unroll
            for (int mf = 0; mf < 4; mf++)
                ldsm4(a[mf], base + aoff[mf] + ((((ks << 1) + u0) ^ axr[mf]) << 4));
#pragma unroll
            for (int nf = 0; nf < 10; nf++)
                ldsm2(bh[nf], base + 32768 + noff[nf] + ((((ks << 1) + u1) ^ nxr[nf]) << 4));
#pragma unroll
            for (int nf = 0; nf < 10; nf++)
                ldsm2(bl[nf], base + 73728 + noff[nf] + ((((ks << 1) + u1) ^ nxr[nf]) << 4));
            // Ah*Bh + Ah*Bl
#pragma unroll
            for (int mf = 0; mf < 4; mf++)
#pragma unroll
                for (int nf = 0; nf < 10; nf++) mma16816(acc[mf][nf], a[mf], bh[nf]);
#pragma unroll
            for (int mf = 0; mf < 4; mf++)
#pragma unroll
                for (int nf = 0; nf < 10; nf++) mma16816(acc[mf][nf], a[mf], bl[nf]);
            // Al*Bh (reuse A regs)
#pragma unroll
            for (int mf = 0; mf < 4; mf++)
                ldsm4(a[mf], base + 16384 + aoff[mf] + ((((ks << 1) + u0) ^ axr[mf]) << 4));
#pragma unroll
            for (int mf = 0; mf < 4; mf++)
#pragma unroll
                for (int nf = 0; nf < 10; nf++) mma16816(acc[mf][nf], a[mf], bh[nf]);
        }
        __syncthreads();
        if (c + 2 < NCHUNK && tid == 0)
            hmma_issue(sb, s, kbase + (c + 2) * 64, m0, pAh, pAl, pBh, pBl);
    }

    // epilogue: write fp32 partial
    float* C = g_ep[z][kz];
#pragma unroll
    for (int mf = 0; mf < 4; mf++) {
        int r0 = m0 + wm * 64 + mf * 16 + (lane >> 2);
#pragma unroll
        for (int nf = 0; nf < 10; nf++) {
            int col = wn * 80 + nf * 8 + (lane & 3) * 2;
            if (col < EE) {
                *(float2*)&C[(size_t)r0 * EE + col]       = make_float2(acc[mf][nf][0], acc[mf][nf][1]);
                *(float2*)&C[(size_t)(r0 + 8) * EE + col] = make_float2(acc[mf][nf][2], acc[mf][nf][3]);
            }
        }
    }
}

// ---------------- fp32 GEMM for xz = (p0+p1) @ W_x ----------------
#define APAD 264

__global__ __launch_bounds__(256, 2)
void gemm_kernel(const float* __restrict__ Bv0, const float* __restrict__ Bv1)
{
    const int N = 512, K = EE, ldb = 512, ldc = 512;
    int z = blockIdx.z;
    const float* A0 = g_ep[z][0];
    const float* A1 = g_ep[z][1];
    const float* Bm = z ? Bv1 : Bv0;
    float* C = g_xz[z];

    __shared__ __align__(16) float As[2][8][APAD];
    __shared__ __align__(16) float Bs[2][8][128];

    int tid = threadIdx.x;
    int tx = tid & 15, ty = tid >> 4;
    int m0 = blockIdx.y * 128;
    int n0 = blockIdx.x * 128;

    unsigned long long acc[8][4];
#pragma unroll
    for (int i = 0; i < 8; i++)
#pragma unroll
        for (int j = 0; j < 4; j++) acc[i][j] = 0ULL;

    int numK = (K + 7) / 8;   // 38

    float2 av[2]; float4 bv;
    // load k-tile 0
    auto load_regs = [&](int k0) {
#pragma unroll
        for (int j = 0; j < 2; j++) {
            int l  = tid + 256 * j;
            int am = l >> 2;
            int ak = (l & 3) * 2;
            int k  = k0 + ak;
            float2 v = make_float2(0.f, 0.f);
            size_t off = (size_t)(m0 + am) * EE + k;
            if (k + 1 < K) {
                float2 p = *(const float2*)(A0 + off);
                float2 q = *(const float2*)(A1 + off);
                v.x = p.x + q.x; v.y = p.y + q.y;
            } else if (k < K) {
                v.x = A0[off] + A1[off];
            }
            av[j] = v;
        }
        int bk = tid >> 5, bn = (tid & 31) * 4;
        int k = k0 + bk;
        float4 v = make_float4(0.f, 0.f, 0.f, 0.f);
        if (k < K) v = *(const float4*)(Bm + (size_t)k * ldb + n0 + bn);
        bv = v;
    };
    auto store_smem = [&](float (*Asb)[APAD], float (*Bsb)[128]) {
#pragma unroll
        for (int j = 0; j < 2; j++) {
            int l  = tid + 256 * j;
            int am = l >> 2;
            int ak = (l & 3) * 2;
            *(float2*)&Asb[ak][2 * am]     = make_float2(av[j].x, av[j].x);
            *(float2*)&Asb[ak + 1][2 * am] = make_float2(av[j].y, av[j].y);
        }
        int bk = tid >> 5, bn = (tid & 31) * 4;
        *(float4*)&Bsb[bk][bn] = bv;
    };

    load_regs(0);
    store_smem(As[0], Bs[0]);
    __syncthreads();

    for (int kt = 0; kt < numK; kt++) {
        int cur = kt & 1;
        bool hn = (kt + 1) < numK;
        if (hn) load_regs((kt + 1) * 8);

#pragma unroll
        for (int kk = 0; kk < 8; kk++) {
            const float* ar = &As[cur][kk][16 * ty];
            ulonglong2 a01 = *(const ulonglong2*)(ar);
            ulonglong2 a23 = *(const ulonglong2*)(ar + 4);
            ulonglong2 a45 = *(const ulonglong2*)(ar + 8);
            ulonglong2 a67 = *(const ulonglong2*)(ar + 12);
            ulonglong2 b01 = *(const ulonglong2*)&Bs[cur][kk][tx * 4];
            ulonglong2 b23 = *(const ulonglong2*)&Bs[cur][kk][64 + tx * 4];
            unsigned long long ad[8] = {a01.x, a01.y, a23.x, a23.y,
                                        a45.x, a45.y, a67.x, a67.y};
#pragma unroll
            for (int i = 0; i < 8; i++) {
                acc[i][0] = ffma2(ad[i], b01.x, acc[i][0]);
                acc[i][1] = ffma2(ad[i], b01.y, acc[i][1]);
                acc[i][2] = ffma2(ad[i], b23.x, acc[i][2]);
                acc[i][3] = ffma2(ad[i], b23.y, acc[i][3]);
            }
        }
        if (hn) store_smem(As[cur ^ 1], Bs[cur ^ 1]);
        __syncthreads();
    }

#pragma unroll
    for (int i = 0; i < 8; i++) {
        int m = m0 + ty * 8 + i;
        float* crow = C + (size_t)m * ldc;
        float2 v0 = unpack2(acc[i][0]);
        float2 v1 = unpack2(acc[i][1]);
        float2 v2 = unpack2(acc[i][2]);
        float2 v3 = unpack2(acc[i][3]);
        *(float4*)&crow[n0 + tx * 4]      = make_float4(v0.x, v0.y, v1.x, v1.y);
        *(float4*)&crow[n0 + 64 + tx * 4] = make_float4(v2.x, v2.y, v3.x, v3.y);
    }
}

// ---------------- LSTM recurrent kernel (unchanged) ----------------
__global__ __launch_bounds__(128)
void lstm_kernel(const float* __restrict__ W1, const float* __restrict__ W2,
                 const float* __restrict__ lng1, const float* __restrict__ lnb1,
                 const float* __restrict__ lng2, const float* __restrict__ lnb2)
{
    int which = blockIdx.y;
    const float* Wh  = (which ? W2 : W1) + 300 * 512;
    const float* lng = which ? lng2 : lng1;
    const float* lnb = which ? lnb2 : lnb1;
    const float* xz  = g_xz[which];
    float* o_out     = g_o[which];

    int b0  = blockIdx.x * 4;
    int tid = threadIdx.x;
    int lane = tid & 31, warp = tid >> 5;

    __shared__ float hs[128][4];
    __shared__ float cs[4][128];
    __shared__ float zs[4][512];
    __shared__ float red[4][2][4];

#pragma unroll
    for (int r = 0; r < 4; r++) { hs[tid][r] = 0.f; cs[r][tid] = 0.f; }
    __syncthreads();

    int c0 = tid * 4;
    int gate = warp;
    int jg = lane * 4;
    float gg[4], gb[4];
#pragma unroll
    for (int i = 0; i < 4; i++) {
        gg[i] = lng[gate * 128 + jg + i];
        gb[i] = lnb[gate * 128 + jg + i];
    }
    float g5 = lng[4 * 128 + tid], b5 = lnb[4 * 128 + tid];

    for (int t = 0; t < TT; t++) {
        unsigned long long acc[4][2];
#pragma unroll
        for (int r = 0; r < 4; r++) {
            float4 x = *(const float4*)&xz[((size_t)(b0 + r) * TT + t) * 512 + c0];
            acc[r][0] = pack2(x.x, x.y);
            acc[r][1] = pack2(x.z, x.w);
        }
#pragma unroll 4
        for (int k = 0; k < 128; k++) {
            float4 w = *(const float4*)&Wh[(size_t)k * 512 + c0];
            unsigned long long w01 = pack2(w.x, w.y);
            unsigned long long w23 = pack2(w.z, w.w);
            float4 h4 = *(const float4*)&hs[k][0];
            unsigned long long h0 = pack2(h4.x, h4.x);
            unsigned long long h1 = pack2(h4.y, h4.y);
            unsigned long long h2 = pack2(h4.z, h4.z);
            unsigned long long h3 = pack2(h4.w, h4.w);
            acc[0][0] = ffma2(h0, w01, acc[0][0]); acc[0][1] = ffma2(h0, w23, acc[0][1]);
            acc[1][0] = ffma2(h1, w01, acc[1][0]); acc[1][1] = ffma2(h1, w23, acc[1][1]);
            acc[2][0] = ffma2(h2, w01, acc[2][0]); acc[2][1] = ffma2(h2, w23, acc[2][1]);
            acc[3][0] = ffma2(h3, w01, acc[3][0]); acc[3][1] = ffma2(h3, w23, acc[3][1]);
        }

#pragma unroll
        for (int r = 0; r < 4; r++) {
            float2 p0 = unpack2(acc[r][0]), p1 = unpack2(acc[r][1]);
            float v0 = p0.x, v1 = p0.y, v2 = p1.x, v3 = p1.y;
            float s  = v0 + v1 + v2 + v3;
            float ss = v0 * v0 + v1 * v1 + v2 * v2 + v3 * v3;
#pragma unroll
            for (int off = 16; off > 0; off >>= 1) {
                s  += __shfl_xor_sync(0xffffffffu, s,  off);
                ss += __shfl_xor_sync(0xffffffffu, ss, off);
            }
            float mu  = s * (1.f / 128.f);
            float var = ss * (1.f / 128.f) - mu * mu;
            float inv = rsqrtf(var + 1e-12f);
            zs[r][c0 + 0] = (v0 - mu) * inv * gg[0] + gb[0];
            zs[r][c0 + 1] = (v1 - mu) * inv * gg[1] + gb[1];
            zs[r][c0 + 2] = (v2 - mu) * inv * gg[2] + gb[2];
            zs[r][c0 + 3] = (v3 - mu) * inv * gg[3] + gb[3];
        }
        __syncthreads();

        int j = tid;
        float cn[4], og[4];
#pragma unroll
        for (int r = 0; r < 4; r++) {
            float ig = zs[r][j];
            float jj = zs[r][128 + j];
            float fg = zs[r][256 + j];
            og[r]    = zs[r][384 + j];
            float c_new = cs[r][j] * sigm(fg + 1.0f) + sigm(ig) * fmaxf(jj, 0.f);
            cs[r][j] = c_new;
            cn[r] = c_new;
            float s = c_new, ss = c_new * c_new;
#pragma unroll
            for (int off = 16; off > 0; off >>= 1) {
                s  += __shfl_xor_sync(0xffffffffu, s,  off);
                ss += __shfl_xor_sync(0xffffffffu, ss, off);
            }
            if (lane == 0) { red[r][0][warp] = s; red[r][1][warp] = ss; }
        }
        __syncthreads();

        float hout[4];
#pragma unroll
        for (int r = 0; r < 4; r++) {
            float S  = red[r][0][0] + red[r][0][1] + red[r][0][2] + red[r][0][3];
            float SS = red[r][1][0] + red[r][1][1] + red[r][1][2] + red[r][1][3];
            float mu  = S * (1.f / 128.f);
            float var = SS * (1.f / 128.f) - mu * mu;
            float hn = fmaxf((cn[r] - mu) * rsqrtf(var + 1e-12f) * g5 + b5, 0.f) * sigm(og[r]);
            hout[r] = hn;
            o_out[((size_t)(b0 + r) * TT + t) * 128 + j] = hn;
        }
        *(float4*)&hs[j][0] = make_float4(hout[0], hout[1], hout[2], hout[3]);
        __syncthreads();
    }
}

// ---------------- attention (unchanged) ----------------
__global__ __launch_bounds__(128)
void attn_kernel(const float* __restrict__ v1, const float* __restrict__ Wo1, const float* __restrict__ bo1,
                 const float* __restrict__ v2, const float* __restrict__ Wo2, const float* __restrict__ bo2)
{
    int which = blockIdx.y, b = blockIdx.x;
    const float* v  = which ? v2  : v1;
    const float* Wo = which ? Wo2 : Wo1;
    const float* bo = which ? bo2 : bo1;
    const float* o  = g_o[which] + (size_t)b * TT * 128;
    float* a        = g_a[which] + (size_t)b * 512;

    int tid = threadIdx.x, lane = tid & 31, warp = tid >> 5;
    __shared__ float al[TT];
    __shared__ float ctxs[128];

    float4 vv = *(const float4*)&v[lane * 4];
    for (int t = warp; t < TT; t += 4) {
        float4 ov = *(const float4*)&o[t * 128 + lane * 4];
        float p = ov.x * vv.x + ov.y * vv.y + ov.z * vv.z + ov.w * vv.w;
#pragma unroll
        for (int off = 16; off > 0; off >>= 1) p += __shfl_xor_sync(0xffffffffu, p, off);
        if (lane == 0) al[t] = p;
    }
    __syncthreads();

    if (warp == 0) {
        float s0 = (lane < TT)      ? al[lane]      : -1e30f;
        float s1 = (lane + 32 < TT) ? al[lane + 32] : -1e30f;
        float m = fmaxf(s0, s1);
#pragma unroll
        for (int off = 16; off > 0; off >>= 1) m = fmaxf(m, __shfl_xor_sync(0xffffffffu, m, off));
        float e0 = (lane < TT)      ? expf(s0 - m) : 0.f;
        float e1 = (lane + 32 < TT) ? expf(s1 - m) : 0.f;
        float s = e0 + e1;
#pragma unroll
        for (int off = 16; off > 0; off >>= 1) s += __shfl_xor_sync(0xffffffffu, s, off);
        float inv = 1.f / s;
        if (lane < TT)      al[lane]      = e0 * inv;
        if (lane + 32 < TT) al[lane + 32] = e1 * inv;
    }
    __syncthreads();

    float cx = 0.f;
    for (int t = 0; t < TT; t++) cx += al[t] * o[t * 128 + tid];
    ctxs[tid] = cx;
    __syncthreads();

    int c0 = tid * 4;
    float4 accv = *(const float4*)&bo[c0];
#pragma unroll 4
    for (int k = 0; k < 128; k++) {
        float4 w = *(const float4*)&Wo[(size_t)k * 512 + c0];
        float x = ctxs[k];
        accv.x += x * w.x; accv.y += x * w.y; accv.z += x * w.z; accv.w += x * w.w;
    }
    a[c0 + 0] = fmaxf(accv.x, 0.f);
    a[c0 + 1] = fmaxf(accv.y, 0.f);
    a[c0 + 2] = fmaxf(accv.z, 0.f);
    a[c0 + 3] = fmaxf(accv.w, 0.f);
}

// ---------------- head (unchanged) ----------------
__global__ __launch_bounds__(128)
void head_kernel(const float* __restrict__ Wh, const float* __restrict__ bh,
                 const float* __restrict__ Wout, const float* __restrict__ bout,
                 float* __restrict__ out)
{
    int b = blockIdx.x, tid = threadIdx.x;
    int lane = tid & 31, warp = tid >> 5;
    __shared__ float cat[1024];
    __shared__ float hid[512];
    __shared__ float red[2][4];

#pragma unroll
    for (int i = 0; i < 8; i++) {
        int k = tid + 128 * i;
        cat[k] = (k < 512) ? g_a[0][(size_t)b * 512 + k] : g_a[1][(size_t)b * 512 + k - 512];
    }
    __syncthreads();

    int c0 = tid * 4;
    float4 acc = *(const float4*)&bh[c0];
#pragma unroll 4
    for (int k = 0; k < 1024; k++) {
        float4 w = *(const float4*)&Wh[(size_t)k * 512 + c0];
        float x = cat[k];
        acc.x += x * w.x; acc.y += x * w.y; acc.z += x * w.z; acc.w += x * w.w;
    }
    hid[c0 + 0] = fmaxf(acc.x, 0.f);
    hid[c0 + 1] = fmaxf(acc.y, 0.f);
    hid[c0 + 2] = fmaxf(acc.z, 0.f);
    hid[c0 + 3] = fmaxf(acc.w, 0.f);
    __syncthreads();

    float p0 = 0.f, p1 = 0.f;
#pragma unroll
    for (int i = 0; i < 4; i++) {
        float h = hid[c0 + i];
        p0 += h * Wout[(c0 + i) * 2 + 0];
        p1 += h * Wout[(c0 + i) * 2 + 1];
    }
#pragma unroll
    for (int off = 16; off > 0; off >>= 1) {
        p0 += __shfl_xor_sync(0xffffffffu, p0, off);
        p1 += __shfl_xor_sync(0xffffffffu, p1, off);
    }
    if (lane == 0) { red[0][warp] = p0; red[1][warp] = p1; }
    __syncthreads();
    if (tid == 0) {
        out[b * 2 + 0] = red[0][0] + red[0][1] + red[0][2] + red[0][3] + bout[0];
        out[b * 2 + 1] = red[1][0] + red[1][1] + red[1][2] + red[1][3] + bout[1];
    }
}

// ---------------- host: tensor maps + launch ----------------
typedef CUresult (*PFN_tmapEnc)(CUtensorMap*, CUtensorMapDataType, cuuint32_t, void*,
                                const cuuint64_t*, const cuuint64_t*, const cuuint32_t*,
                                const cuuint32_t*, CUtensorMapInterleave, CUtensorMapSwizzle,
                                CUtensorMapL2promotion, CUtensorMapFloatOOBfill);

static CUtensorMap s_maps[8];   // Ah0 Al0 Bh0 Bl0 Ah1 Al1 Bh1 Bl1
static int s_init = 0;

static void make_map(PFN_tmapEnc fn, CUtensorMap* m, void* ptr,
                     unsigned long long rows, unsigned boxRows)
{
    cuuint64_t dims[2]    = {KPAD, rows};
    cuuint64_t strides[1] = {KPAD * 2ULL};
    cuuint32_t box[2]     = {64, boxRows};
    cuuint32_t es[2]      = {1, 1};
    fn(m, CU_TENSOR_MAP_DATA_TYPE_BFLOAT16, 2, ptr, dims, strides, box, es,
       CU_TENSOR_MAP_INTERLEAVE_NONE, CU_TENSOR_MAP_SWIZZLE_128B,
       CU_TENSOR_MAP_L2_PROMOTION_L2_128B, CU_TENSOR_MAP_FLOAT_OOB_FILL_NONE);
}

extern "C" void kernel_launch(void* const* d_in, const int* in_sizes, int n_in,
                              void* d_out, int out_size)
{
    const float* x1     = (const float*)d_in[0];
    const float* x2     = (const float*)d_in[1];
    const float* embed1 = (const float*)d_in[2];
    const float* embed2 = (const float*)d_in[3];
    const float* Wl1    = (const float*)d_in[4];
    const float* Wl2    = (const float*)d_in[5];
    const float* lng1   = (const float*)d_in[6];
    const float* lnb1   = (const float*)d_in[7];
    const float* lng2   = (const float*)d_in[8];
    const float* lnb2   = (const float*)d_in[9];
    const float* av1    = (const float*)d_in[10];
    const float* aWo1   = (const float*)d_in[11];
    const float* abo1   = (const float*)d_in[12];
    const float* av2    = (const float*)d_in[13];
    const float* aWo2   = (const float*)d_in[14];
    const float* abo2   = (const float*)d_in[15];
    const float* Wh     = (const float*)d_in[16];
    const float* bh     = (const float*)d_in[17];
    const float* Wout   = (const float*)d_in[18];
    const float* bout   = (const float*)d_in[19];
    float* out = (float*)d_out;

    if (!s_init) {
        cudaFuncSetAttribute(hmma_kernel,
                             cudaFuncAttributeMaxDynamicSharedMemorySize, SMEM_H);
        PFN_tmapEnc fn = nullptr;
        cudaDriverEntryPointQueryResult qr;
        cudaGetDriverEntryPoint("cuTensorMapEncodeTiled", (void**)&fn,
                                cudaEnableDefault, &qr);
        void *pxh, *pxl, *peh, *pel;
        cudaGetSymbolAddress(&pxh, g_xhi);
        cudaGetSymbolAddress(&pxl, g_xlo);
        cudaGetSymbolAddress(&peh, g_ehT);
        cudaGetSymbolAddress(&pel, g_elT);
        size_t xs = (size_t)MROWS * KPAD * 2;   // bytes per z for x arrays
        size_t es = (size_t)NPAD * KPAD * 2;
        make_map(fn, &s_maps[0], (char*)pxh,        MROWS, 128);
        make_map(fn, &s_maps[1], (char*)pxl,        MROWS, 128);
        make_map(fn, &s_maps[2], (char*)peh,        NPAD,  160);
        make_map(fn, &s_maps[3], (char*)pel,        NPAD,  160);
        make_map(fn, &s_maps[4], (char*)pxh + xs,   MROWS, 128);
        make_map(fn, &s_maps[5], (char*)pxl + xs,   MROWS, 128);
        make_map(fn, &s_maps[6], (char*)peh + es,   NPAD,  160);
        make_map(fn, &s_maps[7], (char*)pel + es,   NPAD,  160);
        s_init = 1;
    }

    // 0-3) bf16 hi/lo splits
    convE_kernel<<<(NPAD*KPAD/8 + 255)/256, 256>>>(embed1, 0);
    convE_kernel<<<(NPAD*KPAD/8 + 255)/256, 256>>>(embed2, 1);
    convx_kernel<<<(int)((size_t)MROWS*KPAD/8/256), 256>>>(x1, 0);
    convx_kernel<<<(int)((size_t)MROWS*KPAD/8/256), 256>>>(x2, 1);

    // 4,5) e-partials = x @ embed via HMMA + TMA (index 5 profiled)
    hmma_kernel<<<dim3(2, 46), 256, SMEM_H>>>(0,
        s_maps[0], s_maps[1], s_maps[2], s_maps[3],
        s_maps[4], s_maps[5], s_maps[6], s_maps[7]);
    hmma_kernel<<<dim3(2, 46), 256, SMEM_H>>>(1,
        s_maps[0], s_maps[1], s_maps[2], s_maps[3],
        s_maps[4], s_maps[5], s_maps[6], s_maps[7]);

    // 6) xz = (p0+p1) @ W_lstm[0:300,:]
    gemm_kernel<<<dim3(4, 46, 2), 256>>>(Wl1, Wl2);

    // 7) recurrence
    lstm_kernel<<<dim3(32, 2), 128>>>(Wl1, Wl2, lng1, lnb1, lng2, lnb2);
    // 8) attention
    attn_kernel<<<dim3(128, 2), 128>>>(av1, aWo1, abo1, av2, aWo2, abo2);
    // 9) head
    head_kernel<<<128, 128>>>(Wh, bh, Wout, bout, out);
}

// round 11
// speedup vs baseline: 3.6452x; 1.3814x over previous
#include <cuda_runtime.h>
#include <cuda.h>
#include <cuda_bf16.h>
#include <math.h>
#include <stdint.h>

// ---------------- scratch (static device memory; no allocations) ----------------
#define BB 128
#define TT 46
#define VV 8150
#define EE 300
#define HH 128
#define MROWS (BB*TT)   // 5888
#define KPAD 8192
#define NPAD 384

__device__ float g_ep[2][2][MROWS*EE];   // split-K partial embeddings [z][kz][5888,300]
__device__ float g_xz[2][MROWS*512];     // x-part of gates
__device__ float g_o [2][MROWS*HH];      // lstm outputs
__device__ float g_a [2][BB*512];        // attention outputs

// bf16 split operands
__device__ __nv_bfloat16 g_xhi[2][(size_t)MROWS*KPAD];
__device__ __nv_bfloat16 g_xlo[2][(size_t)MROWS*KPAD];
__device__ __nv_bfloat16 g_ehT[2][(size_t)NPAD*KPAD];
__device__ __nv_bfloat16 g_elT[2][(size_t)NPAD*KPAD];

// ---------------- helpers ----------------
__device__ __forceinline__ unsigned long long ffma2(unsigned long long a,
                                                    unsigned long long b,
                                                    unsigned long long c) {
    unsigned long long d;
    asm("fma.rn.f32x2 %0, %1, %2, %3;" : "=l"(d) : "l"(a), "l"(b), "l"(c));
    return d;
}
__device__ __forceinline__ unsigned long long pack2(float x, float y) {
    unsigned long long d;
    asm("mov.b64 %0, {%1, %2};" : "=l"(d) : "r"(__float_as_uint(x)), "r"(__float_as_uint(y)));
    return d;
}
__device__ __forceinline__ float2 unpack2(unsigned long long v) {
    unsigned int lo, hi;
    asm("mov.b64 {%0, %1}, %2;" : "=r"(lo), "=r"(hi) : "l"(v));
    return make_float2(__uint_as_float(lo), __uint_as_float(hi));
}
__device__ __forceinline__ float sigm(float x) { return 1.0f / (1.0f + expf(-x)); }

__device__ __forceinline__ uint32_t smem_u32(const void* p) {
    uint32_t a;
    asm("{ .reg .u64 t; cvta.to.shared.u64 t, %1; cvt.u32.u64 %0, t; }" : "=r"(a) : "l"(p));
    return a;
}

#define MBAR_INIT(a, cnt) asm volatile("mbarrier.init.shared.b64 [%0], %1;" :: "r"(a), "r"(cnt) : "memory")
#define MBAR_EXPECT_TX(a, b) asm volatile("mbarrier.arrive.expect_tx.shared.b64 _, [%0], %1;" :: "r"(a), "r"(b) : "memory")
#define MBAR_WAIT(a, ph) do { \
    uint32_t _m = (a), _p = (ph), _d; \
    asm volatile("{ .reg .pred p; mbarrier.try_wait.parity.acquire.cta.shared::cta.b64 p, [%1], %2; selp.b32 %0,1,0,p; }" \
        : "=r"(_d) : "r"(_m), "r"(_p) : "memory"); \
    if (!_d) { \
        asm volatile("{ .reg .pred P1; WL_%=: mbarrier.try_wait.parity.acquire.cta.shared::cta.b64 P1, [%0], %1, 0x989680; @P1 bra.uni WD_%=; bra.uni WL_%=; WD_%=: }" \
            :: "r"(_m), "r"(_p) : "memory"); \
    } } while (0)

__device__ __forceinline__ void tma2d(uint32_t smem, const CUtensorMap* m,
                                      int x, int y, uint32_t mbar) {
    asm volatile(
        "cp.async.bulk.tensor.2d.shared::cta.global.tile.mbarrier::complete_tx::bytes "
        "[%0], [%1, {%2, %3}], [%4];"
        :: "r"(smem), "l"(m), "r"(x), "r"(y), "r"(mbar) : "memory");
}

__device__ __forceinline__ void ldsm4(uint32_t* r, uint32_t a) {
    asm volatile("ldmatrix.sync.aligned.m8n8.x4.shared.b16 {%0,%1,%2,%3}, [%4];"
        : "=r"(r[0]), "=r"(r[1]), "=r"(r[2]), "=r"(r[3]) : "r"(a));
}
__device__ __forceinline__ void ldsm2(uint32_t* r, uint32_t a) {
    asm volatile("ldmatrix.sync.aligned.m8n8.x2.shared.b16 {%0,%1}, [%2];"
        : "=r"(r[0]), "=r"(r[1]) : "r"(a));
}
__device__ __forceinline__ void mma16816(float* d, const uint32_t* a, const uint32_t* b) {
    asm volatile("mma.sync.aligned.m16n8k16.row.col.f32.bf16.bf16.f32 "
        "{%0,%1,%2,%3}, {%4,%5,%6,%7}, {%8,%9}, {%0,%1,%2,%3};"
        : "+f"(d[0]), "+f"(d[1]), "+f"(d[2]), "+f"(d[3])
        : "r"(a[0]), "r"(a[1]), "r"(a[2]), "r"(a[3]), "r"(b[0]), "r"(b[1]));
}

// ---------------- conversion kernels ----------------
__global__ __launch_bounds__(256)
void convx_kernel(const float* __restrict__ x, int z)
{
    size_t idx = (size_t)blockIdx.x * 256 + threadIdx.x;
    int row = (int)(idx >> 10);
    int kk  = (int)(idx & 1023) << 3;
    __align__(16) __nv_bfloat16 h[8], l[8];
#pragma unroll
    for (int j = 0; j < 8; j++) {
        int k = kk + j;
        float v = (k < VV) ? x[(size_t)row * VV + k] : 0.f;
        __nv_bfloat16 hb = __float2bfloat16(v);
        h[j] = hb;
        l[j] = __float2bfloat16(v - __bfloat162float(hb));
    }
    size_t o = (size_t)row * KPAD + kk;
    *(uint4*)&g_xhi[z][o] = *(uint4*)h;
    *(uint4*)&g_xlo[z][o] = *(uint4*)l;
}

__global__ __launch_bounds__(256)
void convE_kernel(const float* __restrict__ embed, int z)
{
    size_t idx = (size_t)blockIdx.x * 256 + threadIdx.x;
    int n  = (int)(idx >> 10);
    int kk = (int)(idx & 1023) << 3;
    __align__(16) __nv_bfloat16 h[8], l[8];
#pragma unroll
    for (int j = 0; j < 8; j++) {
        int k = kk + j;
        float v = (n < EE && k < VV) ? embed[(size_t)k * EE + n] : 0.f;
        __nv_bfloat16 hb = __float2bfloat16(v);
        h[j] = hb;
        l[j] = __float2bfloat16(v - __bfloat162float(hb));
    }
    size_t o = (size_t)n * KPAD + kk;
    *(uint4*)&g_ehT[z][o] = *(uint4*)h;
    *(uint4*)&g_elT[z][o] = *(uint4*)l;
}

// ---------------- HMMA bf16-split GEMM with TMA ----------------
// CTA: M=64, N=160, K=4096 (split-K 2), Kc=64.
// Stage: Ahi 8K | Alo 8K | Bhi 20K | Blo 20K = 56K. 2 stages -> 112K (+64).
// 256 threads, 8 warps as 2(M)x4(N); warp tile 32x40. acc = 40 regs/thread.
#define STG_B   57344
#define SMEM_H  (2*STG_B + 64)
#define NCHUNK  64

__device__ __forceinline__ void hmma_issue(uint32_t sb, int s, int k0, int m0, int n0,
    const CUtensorMap* pAh, const CUtensorMap* pAl,
    const CUtensorMap* pBh, const CUtensorMap* pBl)
{
    uint32_t mb = sb + 2*STG_B + 8*s;
    uint32_t base = sb + s*STG_B;
    MBAR_EXPECT_TX(mb, STG_B);
    tma2d(base,         pAh, k0, m0, mb);
    tma2d(base + 8192,  pAl, k0, m0, mb);
    tma2d(base + 16384, pBh, k0, n0, mb);
    tma2d(base + 36864, pBl, k0, n0, mb);
}

__global__ __launch_bounds__(256, 2)
void hmma_kernel(
    const __grid_constant__ CUtensorMap mAh0, const __grid_constant__ CUtensorMap mAl0,
    const __grid_constant__ CUtensorMap mBh0, const __grid_constant__ CUtensorMap mBl0,
    const __grid_constant__ CUtensorMap mAh1, const __grid_constant__ CUtensorMap mAl1,
    const __grid_constant__ CUtensorMap mBh1, const __grid_constant__ CUtensorMap mBl1)
{
    extern __shared__ __align__(1024) char smem[];
    uint32_t sb = smem_u32(smem);
    int tid = threadIdx.x, lane = tid & 31, wid = tid >> 5;
    int z  = blockIdx.z;
    int kz = blockIdx.x & 1;
    int n0 = (blockIdx.x >> 1) * 160;
    int m0 = blockIdx.y * 64;
    int wm = wid & 1, wn = wid >> 1;

    const CUtensorMap* pAh = z ? &mAh1 : &mAh0;
    const CUtensorMap* pAl = z ? &mAl1 : &mAl0;
    const CUtensorMap* pBh = z ? &mBh1 : &mBh0;
    const CUtensorMap* pBl = z ? &mBl1 : &mBl0;

    if (tid == 0) { MBAR_INIT(sb + 2*STG_B, 1); MBAR_INIT(sb + 2*STG_B + 8, 1); }
    __syncthreads();

    int kbase = kz * 4096;
    if (tid == 0) {
        hmma_issue(sb, 0, kbase,      m0, n0, pAh, pAl, pBh, pBl);
        hmma_issue(sb, 1, kbase + 64, m0, n0, pAh, pAl, pBh, pBl);
    }

    int u0 = lane >> 4;              // A: k half (16B unit)
    int u1 = (lane >> 3) & 1;        // B: k half
    int aoff[2], axr[2];
#pragma unroll
    for (int mf = 0; mf < 2; mf++) {
        int mr = wm * 32 + mf * 16 + (lane & 15);
        aoff[mf] = mr * 128;
        axr[mf]  = mr & 7;
    }
    int noff[5], nxr[5];
#pragma unroll
    for (int nf = 0; nf < 5; nf++) {
        int nr = wn * 40 + nf * 8 + (lane & 7);
        noff[nf] = nr * 128;
        nxr[nf]  = nr & 7;
    }

    float acc[2][5][4];
#pragma unroll
    for (int mf = 0; mf < 2; mf++)
#pragma unroll
        for (int nf = 0; nf < 5; nf++)
#pragma unroll
            for (int q = 0; q < 4; q++) acc[mf][nf][q] = 0.f;

    int ph0 = 0, ph1 = 0;
    for (int c = 0; c < NCHUNK; c++) {
        int s = c & 1;
        if (s == 0) { MBAR_WAIT(sb + 2*STG_B, ph0); ph0 ^= 1; }
        else        { MBAR_WAIT(sb + 2*STG_B + 8, ph1); ph1 ^= 1; }
        uint32_t base = sb + s * STG_B;

#pragma unroll
        for (int ks = 0; ks < 4; ks++) {
            uint32_t a[2][4], al[2][4], bh[5][2], bl[5][2];
#pragma unroll
            for (int mf = 0; mf < 2; mf++)
                ldsm4(a[mf], base + aoff[mf] + ((((ks << 1) + u0) ^ axr[mf]) << 4));
#pragma unroll
            for (int nf = 0; nf < 5; nf++)
                ldsm2(bh[nf], base + 16384 + noff[nf] + ((((ks << 1) + u1) ^ nxr[nf]) << 4));
#pragma unroll
            for (int mf = 0; mf < 2; mf++)
#pragma unroll
                for (int nf = 0; nf < 5; nf++) mma16816(acc[mf][nf], a[mf], bh[nf]);
#pragma unroll
            for (int mf = 0; mf < 2; mf++)
                ldsm4(al[mf], base + 8192 + aoff[mf] + ((((ks << 1) + u0) ^ axr[mf]) << 4));
#pragma unroll
            for (int mf = 0; mf < 2; mf++)
#pragma unroll
                for (int nf = 0; nf < 5; nf++) mma16816(acc[mf][nf], al[mf], bh[nf]);
#pragma unroll
            for (int nf = 0; nf < 5; nf++)
                ldsm2(bl[nf], base + 36864 + noff[nf] + ((((ks << 1) + u1) ^ nxr[nf]) << 4));
#pragma unroll
            for (int mf = 0; mf < 2; mf++)
#pragma unroll
                for (int nf = 0; nf < 5; nf++) mma16816(acc[mf][nf], a[mf], bl[nf]);
        }
        __syncthreads();
        if (c + 2 < NCHUNK && tid == 0)
            hmma_issue(sb, s, kbase + (c + 2) * 64, m0, n0, pAh, pAl, pBh, pBl);
    }

    float* C = g_ep[z][kz];
#pragma unroll
    for (int mf = 0; mf < 2; mf++) {
        int r0 = m0 + wm * 32 + mf * 16 + (lane >> 2);
#pragma unroll
        for (int nf = 0; nf < 5; nf++) {
            int col = n0 + wn * 40 + nf * 8 + (lane & 3) * 2;
            if (col < EE) {
                *(float2*)&C[(size_t)r0 * EE + col]       = make_float2(acc[mf][nf][0], acc[mf][nf][1]);
                *(float2*)&C[(size_t)(r0 + 8) * EE + col] = make_float2(acc[mf][nf][2], acc[mf][nf][3]);
            }
        }
    }
}

// ---------------- fp32 GEMM for xz = (p0+p1) @ W_x ----------------
#define APAD 264

__global__ __launch_bounds__(256, 2)
void gemm_kernel(const float* __restrict__ Bv0, const float* __restrict__ Bv1)
{
    const int N = 512, K = EE, ldb = 512, ldc = 512;
    int z = blockIdx.z;
    const float* A0 = g_ep[z][0];
    const float* A1 = g_ep[z][1];
    const float* Bm = z ? Bv1 : Bv0;
    float* C = g_xz[z];

    __shared__ __align__(16) float As[2][8][APAD];
    __shared__ __align__(16) float Bs[2][8][128];

    int tid = threadIdx.x;
    int tx = tid & 15, ty = tid >> 4;
    int m0 = blockIdx.y * 128;
    int n0 = blockIdx.x * 128;

    unsigned long long acc[8][4];
#pragma unroll
    for (int i = 0; i < 8; i++)
#pragma unroll
        for (int j = 0; j < 4; j++) acc[i][j] = 0ULL;

    int numK = (K + 7) / 8;

    float2 av[2]; float4 bv;
    auto load_regs = [&](int k0) {
#pragma unroll
        for (int j = 0; j < 2; j++) {
            int l  = tid + 256 * j;
            int am = l >> 2;
            int ak = (l & 3) * 2;
            int k  = k0 + ak;
            float2 v = make_float2(0.f, 0.f);
            size_t off = (size_t)(m0 + am) * EE + k;
            if (k + 1 < K) {
                float2 p = *(const float2*)(A0 + off);
                float2 q = *(const float2*)(A1 + off);
                v.x = p.x + q.x; v.y = p.y + q.y;
            } else if (k < K) {
                v.x = A0[off] + A1[off];
            }
            av[j] = v;
        }
        int bk = tid >> 5, bn = (tid & 31) * 4;
        int k = k0 + bk;
        float4 v = make_float4(0.f, 0.f, 0.f, 0.f);
        if (k < K) v = *(const float4*)(Bm + (size_t)k * ldb + n0 + bn);
        bv = v;
    };
    auto store_smem = [&](float (*Asb)[APAD], float (*Bsb)[128]) {
#pragma unroll
        for (int j = 0; j < 2; j++) {
            int l  = tid + 256 * j;
            int am = l >> 2;
            int ak = (l & 3) * 2;
            *(float2*)&Asb[ak][2 * am]     = make_float2(av[j].x, av[j].x);
            *(float2*)&Asb[ak + 1][2 * am] = make_float2(av[j].y, av[j].y);
        }
        int bk = tid >> 5, bn = (tid & 31) * 4;
        *(float4*)&Bsb[bk][bn] = bv;
    };

    load_regs(0);
    store_smem(As[0], Bs[0]);
    __syncthreads();

    for (int kt = 0; kt < numK; kt++) {
        int cur = kt & 1;
        bool hn = (kt + 1) < numK;
        if (hn) load_regs((kt + 1) * 8);

#pragma unroll
        for (int kk = 0; kk < 8; kk++) {
            const float* ar = &As[cur][kk][16 * ty];
            ulonglong2 a01 = *(const ulonglong2*)(ar);
            ulonglong2 a23 = *(const ulonglong2*)(ar + 4);
            ulonglong2 a45 = *(const ulonglong2*)(ar + 8);
            ulonglong2 a67 = *(const ulonglong2*)(ar + 12);
            ulonglong2 b01 = *(const ulonglong2*)&Bs[cur][kk][tx * 4];
            ulonglong2 b23 = *(const ulonglong2*)&Bs[cur][kk][64 + tx * 4];
            unsigned long long ad[8] = {a01.x, a01.y, a23.x, a23.y,
                                        a45.x, a45.y, a67.x, a67.y};
#pragma unroll
            for (int i = 0; i < 8; i++) {
                acc[i][0] = ffma2(ad[i], b01.x, acc[i][0]);
                acc[i][1] = ffma2(ad[i], b01.y, acc[i][1]);
                acc[i][2] = ffma2(ad[i], b23.x, acc[i][2]);
                acc[i][3] = ffma2(ad[i], b23.y, acc[i][3]);
            }
        }
        if (hn) store_smem(As[cur ^ 1], Bs[cur ^ 1]);
        __syncthreads();
    }

#pragma unroll
    for (int i = 0; i < 8; i++) {
        int m = m0 + ty * 8 + i;
        float* crow = C + (size_t)m * ldc;
        float2 v0 = unpack2(acc[i][0]);
        float2 v1 = unpack2(acc[i][1]);
        float2 v2 = unpack2(acc[i][2]);
        float2 v3 = unpack2(acc[i][3]);
        *(float4*)&crow[n0 + tx * 4]      = make_float4(v0.x, v0.y, v1.x, v1.y);
        *(float4*)&crow[n0 + 64 + tx * 4] = make_float4(v2.x, v2.y, v3.x, v3.y);
    }
}

// ---------------- LSTM recurrent kernel: 256 threads, 2 cols/thread ----------------
__global__ __launch_bounds__(256)
void lstm_kernel(const float* __restrict__ W1, const float* __restrict__ W2,
                 const float* __restrict__ lng1, const float* __restrict__ lnb1,
                 const float* __restrict__ lng2, const float* __restrict__ lnb2)
{
    int which = blockIdx.y;
    const float* Wh  = (which ? W2 : W1) + 300 * 512;
    const float* lng = which ? lng2 : lng1;
    const float* lnb = which ? lnb2 : lnb1;
    const float* xz  = g_xz[which];
    float* o_out     = g_o[which];

    int b0  = blockIdx.x * 4;
    int tid = threadIdx.x;
    int lane = tid & 31, warp = tid >> 5;

    __shared__ __align__(16) unsigned long long hs2[128][4]; // pre-packed (h,h) per [k][row]
    __shared__ float cs[4][128];
    __shared__ float zs[4][512];
    __shared__ float redg[4][4][2][2];   // [row][gate][half][s/ss]
    __shared__ float redc[4][2][4];      // [row][s/ss][warp quadrant]

    if (tid < 128) {
#pragma unroll
        for (int r = 0; r < 4; r++) { hs2[tid][r] = 0ULL; cs[r][tid] = 0.f; }
    }
    __syncthreads();

    int c0 = tid * 2;
    int gate = tid >> 6;
    int ghalf = (tid >> 5) & 1;
    int jg = c0 & 127;
    float gg0 = lng[gate * 128 + jg],     gg1 = lng[gate * 128 + jg + 1];
    float gb0 = lnb[gate * 128 + jg],     gb1 = lnb[gate * 128 + jg + 1];
    int j = tid & 127, rh = tid >> 7;
    float g5 = lng[4 * 128 + j], b5 = lnb[4 * 128 + j];

    for (int t = 0; t < TT; t++) {
        // ---- z = xz[t] + h @ Wh  (thread owns 2 cols for 4 rows) ----
        unsigned long long acc[4];
#pragma unroll
        for (int r = 0; r < 4; r++)
            acc[r] = *(const unsigned long long*)&xz[((size_t)(b0 + r) * TT + t) * 512 + c0];
#pragma unroll 4
        for (int k = 0; k < 128; k++) {
            unsigned long long w = *(const unsigned long long*)&Wh[(size_t)k * 512 + c0];
            ulonglong2 h01 = *(const ulonglong2*)&hs2[k][0];
            ulonglong2 h23 = *(const ulonglong2*)&hs2[k][2];
            acc[0] = ffma2(h01.x, w, acc[0]);
            acc[1] = ffma2(h01.y, w, acc[1]);
            acc[2] = ffma2(h23.x, w, acc[2]);
            acc[3] = ffma2(h23.y, w, acc[3]);
        }

        // ---- per-gate LayerNorm (2 warps per gate, smem combine) ----
#pragma unroll
        for (int r = 0; r < 4; r++) {
            float2 p = unpack2(acc[r]);
            float s  = p.x + p.y;
            float ss = p.x * p.x + p.y * p.y;
#pragma unroll
            for (int off = 16; off > 0; off >>= 1) {
                s  += __shfl_xor_sync(0xffffffffu, s,  off);
                ss += __shfl_xor_sync(0xffffffffu, ss, off);
            }
            if (lane == 0) { redg[r][gate][ghalf][0] = s; redg[r][gate][ghalf][1] = ss; }
        }
        __syncthreads();
#pragma unroll
        for (int r = 0; r < 4; r++) {
            float S  = redg[r][gate][0][0] + redg[r][gate][1][0];
            float SS = redg[r][gate][0][1] + redg[r][gate][1][1];
            float mu  = S * (1.f / 128.f);
            float var = SS * (1.f / 128.f) - mu * mu;
            float inv = rsqrtf(var + 1e-12f);
            float2 p = unpack2(acc[r]);
            zs[r][c0]     = (p.x - mu) * inv * gg0 + gb0;
            zs[r][c0 + 1] = (p.y - mu) * inv * gg1 + gb1;
        }
        __syncthreads();

        // ---- cell update + cell LN (thread handles rows 2rh, 2rh+1 at index j) ----
        float cn[2], og[2];
#pragma unroll
        for (int q = 0; q < 2; q++) {
            int r = 2 * rh + q;
            float ig = zs[r][j];
            float jj = zs[r][128 + j];
            float fg = zs[r][256 + j];
            og[q]    = zs[r][384 + j];
            float c_new = cs[r][j] * sigm(fg + 1.0f) + sigm(ig) * fmaxf(jj, 0.f);
            cs[r][j] = c_new;
            cn[q] = c_new;
            float s = c_new, ss = c_new * c_new;
#pragma unroll
            for (int off = 16; off > 0; off >>= 1) {
                s  += __shfl_xor_sync(0xffffffffu, s,  off);
                ss += __shfl_xor_sync(0xffffffffu, ss, off);
            }
            if (lane == 0) { redc[r][0][warp & 3] = s; redc[r][1][warp & 3] = ss; }
        }
        __syncthreads();

        float hout[2];
#pragma unroll
        for (int q = 0; q < 2; q++) {
            int r = 2 * rh + q;
            float S  = redc[r][0][0] + redc[r][0][1] + redc[r][0][2] + redc[r][0][3];
            float SS = redc[r][1][0] + redc[r][1][1] + redc[r][1][2] + redc[r][1][3];
            float mu  = S * (1.f / 128.f);
            float var = SS * (1.f / 128.f) - mu * mu;
            float hn = fmaxf((cn[q] - mu) * rsqrtf(var + 1e-12f) * g5 + b5, 0.f) * sigm(og[q]);
            hout[q] = hn;
            o_out[((size_t)(b0 + r) * TT + t) * 128 + j] = hn;
        }
        hs2[j][2 * rh]     = pack2(hout[0], hout[0]);
        hs2[j][2 * rh + 1] = pack2(hout[1], hout[1]);
        __syncthreads();
    }
}

// ---------------- attention (unchanged) ----------------
__global__ __launch_bounds__(128)
void attn_kernel(const float* __restrict__ v1, const float* __restrict__ Wo1, const float* __restrict__ bo1,
                 const float* __restrict__ v2, const float* __restrict__ Wo2, const float* __restrict__ bo2)
{
    int which = blockIdx.y, b = blockIdx.x;
    const float* v  = which ? v2  : v1;
    const float* Wo = which ? Wo2 : Wo1;
    const float* bo = which ? bo2 : bo1;
    const float* o  = g_o[which] + (size_t)b * TT * 128;
    float* a        = g_a[which] + (size_t)b * 512;

    int tid = threadIdx.x, lane = tid & 31, warp = tid >> 5;
    __shared__ float al[TT];
    __shared__ float ctxs[128];

    float4 vv = *(const float4*)&v[lane * 4];
    for (int t = warp; t < TT; t += 4) {
        float4 ov = *(const float4*)&o[t * 128 + lane * 4];
        float p = ov.x * vv.x + ov.y * vv.y + ov.z * vv.z + ov.w * vv.w;
#pragma unroll
        for (int off = 16; off > 0; off >>= 1) p += __shfl_xor_sync(0xffffffffu, p, off);
        if (lane == 0) al[t] = p;
    }
    __syncthreads();

    if (warp == 0) {
        float s0 = (lane < TT)      ? al[lane]      : -1e30f;
        float s1 = (lane + 32 < TT) ? al[lane + 32] : -1e30f;
        float m = fmaxf(s0, s1);
#pragma unroll
        for (int off = 16; off > 0; off >>= 1) m = fmaxf(m, __shfl_xor_sync(0xffffffffu, m, off));
        float e0 = (lane < TT)      ? expf(s0 - m) : 0.f;
        float e1 = (lane + 32 < TT) ? expf(s1 - m) : 0.f;
        float s = e0 + e1;
#pragma unroll
        for (int off = 16; off > 0; off >>= 1) s += __shfl_xor_sync(0xffffffffu, s, off);
        float inv = 1.f / s;
        if (lane < TT)      al[lane]      = e0 * inv;
        if (lane + 32 < TT) al[lane + 32] = e1 * inv;
    }
    __syncthreads();

    float cx = 0.f;
    for (int t = 0; t < TT; t++) cx += al[t] * o[t * 128 + tid];
    ctxs[tid] = cx;
    __syncthreads();

    int c0 = tid * 4;
    float4 accv = *(const float4*)&bo[c0];
#pragma unroll 4
    for (int k = 0; k < 128; k++) {
        float4 w = *(const float4*)&Wo[(size_t)k * 512 + c0];
        float x = ctxs[k];
        accv.x += x * w.x; accv.y += x * w.y; accv.z += x * w.z; accv.w += x * w.w;
    }
    a[c0 + 0] = fmaxf(accv.x, 0.f);
    a[c0 + 1] = fmaxf(accv.y, 0.f);
    a[c0 + 2] = fmaxf(accv.z, 0.f);
    a[c0 + 3] = fmaxf(accv.w, 0.f);
}

// ---------------- head (unchanged) ----------------
__global__ __launch_bounds__(128)
void head_kernel(const float* __restrict__ Wh, const float* __restrict__ bh,
                 const float* __restrict__ Wout, const float* __restrict__ bout,
                 float* __restrict__ out)
{
    int b = blockIdx.x, tid = threadIdx.x;
    int lane = tid & 31, warp = tid >> 5;
    __shared__ float cat[1024];
    __shared__ float hid[512];
    __shared__ float red[2][4];

#pragma unroll
    for (int i = 0; i < 8; i++) {
        int k = tid + 128 * i;
        cat[k] = (k < 512) ? g_a[0][(size_t)b * 512 + k] : g_a[1][(size_t)b * 512 + k - 512];
    }
    __syncthreads();

    int c0 = tid * 4;
    float4 acc = *(const float4*)&bh[c0];
#pragma unroll 4
    for (int k = 0; k < 1024; k++) {
        float4 w = *(const float4*)&Wh[(size_t)k * 512 + c0];
        float x = cat[k];
        acc.x += x * w.x; acc.y += x * w.y; acc.z += x * w.z; acc.w += x * w.w;
    }
    hid[c0 + 0] = fmaxf(acc.x, 0.f);
    hid[c0 + 1] = fmaxf(acc.y, 0.f);
    hid[c0 + 2] = fmaxf(acc.z, 0.f);
    hid[c0 + 3] = fmaxf(acc.w, 0.f);
    __syncthreads();

    float p0 = 0.f, p1 = 0.f;
#pragma unroll
    for (int i = 0; i < 4; i++) {
        float h = hid[c0 + i];
        p0 += h * Wout[(c0 + i) * 2 + 0];
        p1 += h * Wout[(c0 + i) * 2 + 1];
    }
#pragma unroll
    for (int off = 16; off > 0; off >>= 1) {
        p0 += __shfl_xor_sync(0xffffffffu, p0, off);
        p1 += __shfl_xor_sync(0xffffffffu, p1, off);
    }
    if (lane == 0) { red[0][warp] = p0; red[1][warp] = p1; }
    __syncthreads();
    if (tid == 0) {
        out[b * 2 + 0] = red[0][0] + red[0][1] + red[0][2] + red[0][3] + bout[0];
        out[b * 2 + 1] = red[1][0] + red[1][1] + red[1][2] + red[1][3] + bout[1];
    }
}

// ---------------- host: tensor maps + launch ----------------
typedef CUresult (*PFN_tmapEnc)(CUtensorMap*, CUtensorMapDataType, cuuint32_t, void*,
                                const cuuint64_t*, const cuuint64_t*, const cuuint32_t*,
                                const cuuint32_t*, CUtensorMapInterleave, CUtensorMapSwizzle,
                                CUtensorMapL2promotion, CUtensorMapFloatOOBfill);

static CUtensorMap s_maps[8];   // Ah0 Al0 Bh0 Bl0 Ah1 Al1 Bh1 Bl1
static int s_init = 0;

static void make_map(PFN_tmapEnc fn, CUtensorMap* m, void* ptr,
                     unsigned long long rows, unsigned boxRows)
{
    cuuint64_t dims[2]    = {KPAD, rows};
    cuuint64_t strides[1] = {KPAD * 2ULL};
    cuuint32_t box[2]     = {64, boxRows};
    cuuint32_t es[2]      = {1, 1};
    fn(m, CU_TENSOR_MAP_DATA_TYPE_BFLOAT16, 2, ptr, dims, strides, box, es,
       CU_TENSOR_MAP_INTERLEAVE_NONE, CU_TENSOR_MAP_SWIZZLE_128B,
       CU_TENSOR_MAP_L2_PROMOTION_L2_128B, CU_TENSOR_MAP_FLOAT_OOB_FILL_NONE);
}

extern "C" void kernel_launch(void* const* d_in, const int* in_sizes, int n_in,
                              void* d_out, int out_size)
{
    const float* x1     = (const float*)d_in[0];
    const float* x2     = (const float*)d_in[1];
    const float* embed1 = (const float*)d_in[2];
    const float* embed2 = (const float*)d_in[3];
    const float* Wl1    = (const float*)d_in[4];
    const float* Wl2    = (const float*)d_in[5];
    const float* lng1   = (const float*)d_in[6];
    const float* lnb1   = (const float*)d_in[7];
    const float* lng2   = (const float*)d_in[8];
    const float* lnb2   = (const float*)d_in[9];
    const float* av1    = (const float*)d_in[10];
    const float* aWo1   = (const float*)d_in[11];
    const float* abo1   = (const float*)d_in[12];
    const float* av2    = (const float*)d_in[13];
    const float* aWo2   = (const float*)d_in[14];
    const float* abo2   = (const float*)d_in[15];
    const float* Wh     = (const float*)d_in[16];
    const float* bh     = (const float*)d_in[17];
    const float* Wout   = (const float*)d_in[18];
    const float* bout   = (const float*)d_in[19];
    float* out = (float*)d_out;

    if (!s_init) {
        cudaFuncSetAttribute(hmma_kernel,
                             cudaFuncAttributeMaxDynamicSharedMemorySize, SMEM_H);
        PFN_tmapEnc fn = nullptr;
        cudaDriverEntryPointQueryResult qr;
        cudaGetDriverEntryPoint("cuTensorMapEncodeTiled", (void**)&fn,
                                cudaEnableDefault, &qr);
        void *pxh, *pxl, *peh, *pel;
        cudaGetSymbolAddress(&pxh, g_xhi);
        cudaGetSymbolAddress(&pxl, g_xlo);
        cudaGetSymbolAddress(&peh, g_ehT);
        cudaGetSymbolAddress(&pel, g_elT);
        size_t xs = (size_t)MROWS * KPAD * 2;
        size_t es = (size_t)NPAD * KPAD * 2;
        make_map(fn, &s_maps[0], (char*)pxh,        MROWS, 64);
        make_map(fn, &s_maps[1], (char*)pxl,        MROWS, 64);
        make_map(fn, &s_maps[2], (char*)peh,        NPAD,  160);
        make_map(fn, &s_maps[3], (char*)pel,        NPAD,  160);
        make_map(fn, &s_maps[4], (char*)pxh + xs,   MROWS, 64);
        make_map(fn, &s_maps[5], (char*)pxl + xs,   MROWS, 64);
        make_map(fn, &s_maps[6], (char*)peh + es,   NPAD,  160);
        make_map(fn, &s_maps[7], (char*)pel + es,   NPAD,  160);
        s_init = 1;
    }

    // 0-3) bf16 hi/lo splits
    convE_kernel<<<(NPAD*KPAD/8 + 255)/256, 256>>>(embed1, 0);
    convE_kernel<<<(NPAD*KPAD/8 + 255)/256, 256>>>(embed2, 1);
    convx_kernel<<<(int)((size_t)MROWS*KPAD/8/256), 256>>>(x1, 0);
    convx_kernel<<<(int)((size_t)MROWS*KPAD/8/256), 256>>>(x2, 1);

    // 4) e-partials = x @ embed via HMMA + TMA, both z merged: grid (n*kz, m, z)
    hmma_kernel<<<dim3(4, 92, 2), 256, SMEM_H>>>(
        s_maps[0], s_maps[1], s_maps[2], s_maps[3],
        s_maps[4], s_maps[5], s_maps[6], s_maps[7]);

    // 5) xz = (p0+p1) @ W_lstm[0:300,:]   (profiled launch)
    gemm_kernel<<<dim3(4, 46, 2), 256>>>(Wl1, Wl2);

    // 6) recurrence
    lstm_kernel<<<dim3(32, 2), 256>>>(Wl1, Wl2, lng1, lnb1, lng2, lnb2);
    // 7) attention
    attn_kernel<<<dim3(128, 2), 128>>>(av1, aWo1, abo1, av2, aWo2, abo2);
    // 8) head
    head_kernel<<<128, 128>>>(Wh, bh, Wout, bout, out);
}

// round 15
// speedup vs baseline: 3.6546x; 1.0026x over previous
#include <cuda_runtime.h>
#include <cuda.h>
#include <cuda_bf16.h>
#include <math.h>
#include <stdint.h>

// ---------------- scratch (static device memory; no allocations) ----------------
#define BB 128
#define TT 46
#define VV 8150
#define EE 300
#define HH 128
#define MROWS (BB*TT)   // 5888
#define KPAD 8192
#define NPAD 384

__device__ float g_ep[2][2][MROWS*EE];   // split-K partial embeddings [z][kz][5888,300]
__device__ float g_xz[2][MROWS*512];     // x-part of gates
__device__ float g_o [2][MROWS*HH];      // lstm outputs
__device__ float g_a [2][BB*512];        // attention outputs

// bf16 split operands
__device__ __nv_bfloat16 g_xhi[2][(size_t)MROWS*KPAD];
__device__ __nv_bfloat16 g_xlo[2][(size_t)MROWS*KPAD];
__device__ __nv_bfloat16 g_ehT[2][(size_t)NPAD*KPAD];
__device__ __nv_bfloat16 g_elT[2][(size_t)NPAD*KPAD];

// ---------------- helpers ----------------
__device__ __forceinline__ unsigned long long ffma2(unsigned long long a,
                                                    unsigned long long b,
                                                    unsigned long long c) {
    unsigned long long d;
    asm("fma.rn.f32x2 %0, %1, %2, %3;" : "=l"(d) : "l"(a), "l"(b), "l"(c));
    return d;
}
__device__ __forceinline__ unsigned long long pack2(float x, float y) {
    unsigned long long d;
    asm("mov.b64 %0, {%1, %2};" : "=l"(d) : "r"(__float_as_uint(x)), "r"(__float_as_uint(y)));
    return d;
}
__device__ __forceinline__ float2 unpack2(unsigned long long v) {
    unsigned int lo, hi;
    asm("mov.b64 {%0, %1}, %2;" : "=r"(lo), "=r"(hi) : "l"(v));
    return make_float2(__uint_as_float(lo), __uint_as_float(hi));
}
__device__ __forceinline__ float sigm(float x) { return 1.0f / (1.0f + expf(-x)); }

__device__ __forceinline__ uint32_t smem_u32(const void* p) {
    uint32_t a;
    asm("{ .reg .u64 t; cvta.to.shared.u64 t, %1; cvt.u32.u64 %0, t; }" : "=r"(a) : "l"(p));
    return a;
}

#define MBAR_INIT(a, cnt) asm volatile("mbarrier.init.shared.b64 [%0], %1;" :: "r"(a), "r"(cnt) : "memory")
#define MBAR_EXPECT_TX(a, b) asm volatile("mbarrier.arrive.expect_tx.shared.b64 _, [%0], %1;" :: "r"(a), "r"(b) : "memory")
#define MBAR_WAIT(a, ph) do { \
    uint32_t _m = (a), _p = (ph), _d; \
    asm volatile("{ .reg .pred p; mbarrier.try_wait.parity.acquire.cta.shared::cta.b64 p, [%1], %2; selp.b32 %0,1,0,p; }" \
        : "=r"(_d) : "r"(_m), "r"(_p) : "memory"); \
    if (!_d) { \
        asm volatile("{ .reg .pred P1; WL_%=: mbarrier.try_wait.parity.acquire.cta.shared::cta.b64 P1, [%0], %1, 0x989680; @P1 bra.uni WD_%=; bra.uni WL_%=; WD_%=: }" \
            :: "r"(_m), "r"(_p) : "memory"); \
    } } while (0)

__device__ __forceinline__ void tma2d(uint32_t smem, const CUtensorMap* m,
                                      int x, int y, uint32_t mbar) {
    asm volatile(
        "cp.async.bulk.tensor.2d.shared::cta.global.tile.mbarrier::complete_tx::bytes "
        "[%0], [%1, {%2, %3}], [%4];"
        :: "r"(smem), "l"(m), "r"(x), "r"(y), "r"(mbar) : "memory");
}

__device__ __forceinline__ void ldsm4(uint32_t* r, uint32_t a) {
    asm volatile("ldmatrix.sync.aligned.m8n8.x4.shared.b16 {%0,%1,%2,%3}, [%4];"
        : "=r"(r[0]), "=r"(r[1]), "=r"(r[2]), "=r"(r[3]) : "r"(a));
}
__device__ __forceinline__ void ldsm2(uint32_t* r, uint32_t a) {
    asm volatile("ldmatrix.sync.aligned.m8n8.x2.shared.b16 {%0,%1}, [%2];"
        : "=r"(r[0]), "=r"(r[1]) : "r"(a));
}
__device__ __forceinline__ void mma16816(float* d, const uint32_t* a, const uint32_t* b) {
    asm volatile("mma.sync.aligned.m16n8k16.row.col.f32.bf16.bf16.f32 "
        "{%0,%1,%2,%3}, {%4,%5,%6,%7}, {%8,%9}, {%0,%1,%2,%3};"
        : "+f"(d[0]), "+f"(d[1]), "+f"(d[2]), "+f"(d[3])
        : "r"(a[0]), "r"(a[1]), "r"(a[2]), "r"(a[3]), "r"(b[0]), "r"(b[1]));
}

// ---------------- conversion kernels (z merged into grid.y) ----------------
__global__ __launch_bounds__(256)
void convx_kernel(const float* __restrict__ x0, const float* __restrict__ x1)
{
    int z = blockIdx.y;
    const float* x = z ? x1 : x0;
    size_t idx = (size_t)blockIdx.x * 256 + threadIdx.x;
    int row = (int)(idx >> 10);
    int kk  = (int)(idx & 1023) << 3;
    __align__(16) __nv_bfloat16 h[8], l[8];
#pragma unroll
    for (int j = 0; j < 8; j++) {
        int k = kk + j;
        float v = (k < VV) ? x[(size_t)row * VV + k] : 0.f;
        __nv_bfloat16 hb = __float2bfloat16(v);
        h[j] = hb;
        l[j] = __float2bfloat16(v - __bfloat162float(hb));
    }
    size_t o = (size_t)row * KPAD + kk;
    *(uint4*)&g_xhi[z][o] = *(uint4*)h;
    *(uint4*)&g_xlo[z][o] = *(uint4*)l;
}

__global__ __launch_bounds__(256)
void convE_kernel(const float* __restrict__ e0, const float* __restrict__ e1)
{
    int z = blockIdx.y;
    const float* embed = z ? e1 : e0;
    size_t idx = (size_t)blockIdx.x * 256 + threadIdx.x;
    int n  = (int)(idx >> 10);
    int kk = (int)(idx & 1023) << 3;
    __align__(16) __nv_bfloat16 h[8], l[8];
#pragma unroll
    for (int j = 0; j < 8; j++) {
        int k = kk + j;
        float v = (n < EE && k < VV) ? embed[(size_t)k * EE + n] : 0.f;
        __nv_bfloat16 hb = __float2bfloat16(v);
        h[j] = hb;
        l[j] = __float2bfloat16(v - __bfloat162float(hb));
    }
    size_t o = (size_t)n * KPAD + kk;
    *(uint4*)&g_ehT[z][o] = *(uint4*)h;
    *(uint4*)&g_elT[z][o] = *(uint4*)l;
}

// ---------------- HMMA bf16-split GEMM with TMA (known-good config) ----------------
// CTA: M=64, N=160, K=4096 (split-K 2), Kc=64.
// Stage: Ahi 8K | Alo 8K | Bhi 20K | Blo 20K = 56K. 2 stages -> 112K (+64).
// 256 threads, 8 warps as 2(M)x4(N); warp tile 32x40; acc = 40 regs.
#define STG_B   57344
#define SMEM_H  (2*STG_B + 64)
#define NCHUNK  64

__device__ __forceinline__ void hmma_issue(uint32_t sb, int s, int k0, int m0, int n0,
    const CUtensorMap* pAh, const CUtensorMap* pAl,
    const CUtensorMap* pBh, const CUtensorMap* pBl)
{
    uint32_t mb = sb + 2*STG_B + 8*s;
    uint32_t base = sb + s*STG_B;
    MBAR_EXPECT_TX(mb, STG_B);
    tma2d(base,         pAh, k0, m0, mb);
    tma2d(base + 8192,  pAl, k0, m0, mb);
    tma2d(base + 16384, pBh, k0, n0, mb);
    tma2d(base + 36864, pBl, k0, n0, mb);
}

__global__ __launch_bounds__(256, 2)
void hmma_kernel(
    const __grid_constant__ CUtensorMap mAh0, const __grid_constant__ CUtensorMap mAl0,
    const __grid_constant__ CUtensorMap mBh0, const __grid_constant__ CUtensorMap mBl0,
    const __grid_constant__ CUtensorMap mAh1, const __grid_constant__ CUtensorMap mAl1,
    const __grid_constant__ CUtensorMap mBh1, const __grid_constant__ CUtensorMap mBl1)
{
    extern __shared__ __align__(1024) char smem[];
    uint32_t sb = smem_u32(smem);
    int tid = threadIdx.x, lane = tid & 31, wid = tid >> 5;
    int z  = blockIdx.z;
    int kz = blockIdx.x & 1;
    int n0 = (blockIdx.x >> 1) * 160;
    int m0 = blockIdx.y * 64;
    int wm = wid & 1, wn = wid >> 1;

    const CUtensorMap* pAh = z ? &mAh1 : &mAh0;
    const CUtensorMap* pAl = z ? &mAl1 : &mAl0;
    const CUtensorMap* pBh = z ? &mBh1 : &mBh0;
    const CUtensorMap* pBl = z ? &mBl1 : &mBl0;

    if (tid == 0) { MBAR_INIT(sb + 2*STG_B, 1); MBAR_INIT(sb + 2*STG_B + 8, 1); }
    __syncthreads();

    int kbase = kz * 4096;
    if (tid == 0) {
        hmma_issue(sb, 0, kbase,      m0, n0, pAh, pAl, pBh, pBl);
        hmma_issue(sb, 1, kbase + 64, m0, n0, pAh, pAl, pBh, pBl);
    }

    int u0 = lane >> 4;              // A: k half
    int u1 = (lane >> 3) & 1;        // B: k half
    int aoff[2], axr[2];
#pragma unroll
    for (int mf = 0; mf < 2; mf++) {
        int mr = wm * 32 + mf * 16 + (lane & 15);
        aoff[mf] = mr * 128;
        axr[mf]  = mr & 7;
    }
    int noff[5], nxr[5];
#pragma unroll
    for (int nf = 0; nf < 5; nf++) {
        int nr = wn * 40 + nf * 8 + (lane & 7);
        noff[nf] = nr * 128;
        nxr[nf]  = nr & 7;
    }

    float acc[2][5][4];
#pragma unroll
    for (int mf = 0; mf < 2; mf++)
#pragma unroll
        for (int nf = 0; nf < 5; nf++)
#pragma unroll
            for (int q = 0; q < 4; q++) acc[mf][nf][q] = 0.f;

    int ph0 = 0, ph1 = 0;
    for (int c = 0; c < NCHUNK; c++) {
        int s = c & 1;
        if (s == 0) { MBAR_WAIT(sb + 2*STG_B, ph0); ph0 ^= 1; }
        else        { MBAR_WAIT(sb + 2*STG_B + 8, ph1); ph1 ^= 1; }
        uint32_t base = sb + s * STG_B;

#pragma unroll
        for (int ks = 0; ks < 4; ks++) {
            uint32_t a[2][4], al[2][4], bh[5][2], bl[5][2];
#pragma unroll
            for (int mf = 0; mf < 2; mf++)
                ldsm4(a[mf], base + aoff[mf] + ((((ks << 1) + u0) ^ axr[mf]) << 4));
#pragma unroll
            for (int nf = 0; nf < 5; nf++)
                ldsm2(bh[nf], base + 16384 + noff[nf] + ((((ks << 1) + u1) ^ nxr[nf]) << 4));
#pragma unroll
            for (int mf = 0; mf < 2; mf++)
#pragma unroll
                for (int nf = 0; nf < 5; nf++) mma16816(acc[mf][nf], a[mf], bh[nf]);
#pragma unroll
            for (int mf = 0; mf < 2; mf++)
                ldsm4(al[mf], base + 8192 + aoff[mf] + ((((ks << 1) + u0) ^ axr[mf]) << 4));
#pragma unroll
            for (int mf = 0; mf < 2; mf++)
#pragma unroll
                for (int nf = 0; nf < 5; nf++) mma16816(acc[mf][nf], al[mf], bh[nf]);
#pragma unroll
            for (int nf = 0; nf < 5; nf++)
                ldsm2(bl[nf], base + 36864 + noff[nf] + ((((ks << 1) + u1) ^ nxr[nf]) << 4));
#pragma unroll
            for (int mf = 0; mf < 2; mf++)
#pragma unroll
                for (int nf = 0; nf < 5; nf++) mma16816(acc[mf][nf], a[mf], bl[nf]);
        }
        __syncthreads();
        if (c + 2 < NCHUNK && tid == 0)
            hmma_issue(sb, s, kbase + (c + 2) * 64, m0, n0, pAh, pAl, pBh, pBl);
    }

    float* C = g_ep[z][kz];
#pragma unroll
    for (int mf = 0; mf < 2; mf++) {
        int r0 = m0 + wm * 32 + mf * 16 + (lane >> 2);
#pragma unroll
        for (int nf = 0; nf < 5; nf++) {
            int col = n0 + wn * 40 + nf * 8 + (lane & 3) * 2;
            if (col < EE) {
                *(float2*)&C[(size_t)r0 * EE + col]       = make_float2(acc[mf][nf][0], acc[mf][nf][1]);
                *(float2*)&C[(size_t)(r0 + 8) * EE + col] = make_float2(acc[mf][nf][2], acc[mf][nf][3]);
            }
        }
    }
}

// ---------------- fp32 GEMM for xz = (p0+p1) @ W_x ----------------
#define APAD 264

__global__ __launch_bounds__(256, 2)
void gemm_kernel(const float* __restrict__ Bv0, const float* __restrict__ Bv1)
{
    const int N = 512, K = EE, ldb = 512, ldc = 512;
    int z = blockIdx.z;
    const float* A0 = g_ep[z][0];
    const float* A1 = g_ep[z][1];
    const float* Bm = z ? Bv1 : Bv0;
    float* C = g_xz[z];

    __shared__ __align__(16) float As[2][8][APAD];
    __shared__ __align__(16) float Bs[2][8][128];

    int tid = threadIdx.x;
    int tx = tid & 15, ty = tid >> 4;
    int m0 = blockIdx.y * 128;
    int n0 = blockIdx.x * 128;

    unsigned long long acc[8][4];
#pragma unroll
    for (int i = 0; i < 8; i++)
#pragma unroll
        for (int j = 0; j < 4; j++) acc[i][j] = 0ULL;

    int numK = (K + 7) / 8;

    float2 av[2]; float4 bv;
    auto load_regs = [&](int k0) {
#pragma unroll
        for (int j = 0; j < 2; j++) {
            int l  = tid + 256 * j;
            int am = l >> 2;
            int ak = (l & 3) * 2;
            int k  = k0 + ak;
            float2 v = make_float2(0.f, 0.f);
            size_t off = (size_t)(m0 + am) * EE + k;
            if (k + 1 < K) {
                float2 p = *(const float2*)(A0 + off);
                float2 q = *(const float2*)(A1 + off);
                v.x = p.x + q.x; v.y = p.y + q.y;
            } else if (k < K) {
                v.x = A0[off] + A1[off];
            }
            av[j] = v;
        }
        int bk = tid >> 5, bn = (tid & 31) * 4;
        int k = k0 + bk;
        float4 v = make_float4(0.f, 0.f, 0.f, 0.f);
        if (k < K) v = *(const float4*)(Bm + (size_t)k * ldb + n0 + bn);
        bv = v;
    };
    auto store_smem = [&](float (*Asb)[APAD], float (*Bsb)[128]) {
#pragma unroll
        for (int j = 0; j < 2; j++) {
            int l  = tid + 256 * j;
            int am = l >> 2;
            int ak = (l & 3) * 2;
            *(float2*)&Asb[ak][2 * am]     = make_float2(av[j].x, av[j].x);
            *(float2*)&Asb[ak + 1][2 * am] = make_float2(av[j].y, av[j].y);
        }
        int bk = tid >> 5, bn = (tid & 31) * 4;
        *(float4*)&Bsb[bk][bn] = bv;
    };

    load_regs(0);
    store_smem(As[0], Bs[0]);
    __syncthreads();

    for (int kt = 0; kt < numK; kt++) {
        int cur = kt & 1;
        bool hn = (kt + 1) < numK;
        if (hn) load_regs((kt + 1) * 8);

#pragma unroll
        for (int kk = 0; kk < 8; kk++) {
            const float* ar = &As[cur][kk][16 * ty];
            ulonglong2 a01 = *(const ulonglong2*)(ar);
            ulonglong2 a23 = *(const ulonglong2*)(ar + 4);
            ulonglong2 a45 = *(const ulonglong2*)(ar + 8);
            ulonglong2 a67 = *(const ulonglong2*)(ar + 12);
            ulonglong2 b01 = *(const ulonglong2*)&Bs[cur][kk][tx * 4];
            ulonglong2 b23 = *(const ulonglong2*)&Bs[cur][kk][64 + tx * 4];
            unsigned long long ad[8] = {a01.x, a01.y, a23.x, a23.y,
                                        a45.x, a45.y, a67.x, a67.y};
#pragma unroll
            for (int i = 0; i < 8; i++) {
                acc[i][0] = ffma2(ad[i], b01.x, acc[i][0]);
                acc[i][1] = ffma2(ad[i], b01.y, acc[i][1]);
                acc[i][2] = ffma2(ad[i], b23.x, acc[i][2]);
                acc[i][3] = ffma2(ad[i], b23.y, acc[i][3]);
            }
        }
        if (hn) store_smem(As[cur ^ 1], Bs[cur ^ 1]);
        __syncthreads();
    }

#pragma unroll
    for (int i = 0; i < 8; i++) {
        int m = m0 + ty * 8 + i;
        float* crow = C + (size_t)m * ldc;
        float2 v0 = unpack2(acc[i][0]);
        float2 v1 = unpack2(acc[i][1]);
        float2 v2 = unpack2(acc[i][2]);
        float2 v3 = unpack2(acc[i][3]);
        *(float4*)&crow[n0 + tx * 4]      = make_float4(v0.x, v0.y, v1.x, v1.y);
        *(float4*)&crow[n0 + 64 + tx * 4] = make_float4(v2.x, v2.y, v3.x, v3.y);
    }
}

// ---------------- LSTM recurrent kernel: 256 threads, 2 cols/thread ----------------
__global__ __launch_bounds__(256)
void lstm_kernel(const float* __restrict__ W1, const float* __restrict__ W2,
                 const float* __restrict__ lng1, const float* __restrict__ lnb1,
                 const float* __restrict__ lng2, const float* __restrict__ lnb2)
{
    int which = blockIdx.y;
    const float* Wh  = (which ? W2 : W1) + 300 * 512;
    const float* lng = which ? lng2 : lng1;
    const float* lnb = which ? lnb2 : lnb1;
    const float* xz  = g_xz[which];
    float* o_out     = g_o[which];

    int b0  = blockIdx.x * 4;
    int tid = threadIdx.x;
    int lane = tid & 31, warp = tid >> 5;

    __shared__ __align__(16) unsigned long long hs2[128][4];
    __shared__ float cs[4][128];
    __shared__ float zs[4][512];
    __shared__ float redg[4][4][2][2];
    __shared__ float redc[4][2][4];

    if (tid < 128) {
#pragma unroll
        for (int r = 0; r < 4; r++) { hs2[tid][r] = 0ULL; cs[r][tid] = 0.f; }
    }
    __syncthreads();

    int c0 = tid * 2;
    int gate = tid >> 6;
    int ghalf = (tid >> 5) & 1;
    int jg = c0 & 127;
    float gg0 = lng[gate * 128 + jg],     gg1 = lng[gate * 128 + jg + 1];
    float gb0 = lnb[gate * 128 + jg],     gb1 = lnb[gate * 128 + jg + 1];
    int j = tid & 127, rh = tid >> 7;
    float g5 = lng[4 * 128 + j], b5 = lnb[4 * 128 + j];

    for (int t = 0; t < TT; t++) {
        unsigned long long acc[4];
#pragma unroll
        for (int r = 0; r < 4; r++)
            acc[r] = *(const unsigned long long*)&xz[((size_t)(b0 + r) * TT + t) * 512 + c0];
#pragma unroll 4
        for (int k = 0; k < 128; k++) {
            unsigned long long w = *(const unsigned long long*)&Wh[(size_t)k * 512 + c0];
            ulonglong2 h01 = *(const ulonglong2*)&hs2[k][0];
            ulonglong2 h23 = *(const ulonglong2*)&hs2[k][2];
            acc[0] = ffma2(h01.x, w, acc[0]);
            acc[1] = ffma2(h01.y, w, acc[1]);
            acc[2] = ffma2(h23.x, w, acc[2]);
            acc[3] = ffma2(h23.y, w, acc[3]);
        }

#pragma unroll
        for (int r = 0; r < 4; r++) {
            float2 p = unpack2(acc[r]);
            float s  = p.x + p.y;
            float ss = p.x * p.x + p.y * p.y;
#pragma unroll
            for (int off = 16; off > 0; off >>= 1) {
                s  += __shfl_xor_sync(0xffffffffu, s,  off);
                ss += __shfl_xor_sync(0xffffffffu, ss, off);
            }
            if (lane == 0) { redg[r][gate][ghalf][0] = s; redg[r][gate][ghalf][1] = ss; }
        }
        __syncthreads();
#pragma unroll
        for (int r = 0; r < 4; r++) {
            float S  = redg[r][gate][0][0] + redg[r][gate][1][0];
            float SS = redg[r][gate][0][1] + redg[r][gate][1][1];
            float mu  = S * (1.f / 128.f);
            float var = SS * (1.f / 128.f) - mu * mu;
            float inv = rsqrtf(var + 1e-12f);
            float2 p = unpack2(acc[r]);
            zs[r][c0]     = (p.x - mu) * inv * gg0 + gb0;
            zs[r][c0 + 1] = (p.y - mu) * inv * gg1 + gb1;
        }
        __syncthreads();

        float cn[2], og[2];
#pragma unroll
        for (int q = 0; q < 2; q++) {
            int r = 2 * rh + q;
            float ig = zs[r][j];
            float jj = zs[r][128 + j];
            float fg = zs[r][256 + j];
            og[q]    = zs[r][384 + j];
            float c_new = cs[r][j] * sigm(fg + 1.0f) + sigm(ig) * fmaxf(jj, 0.f);
            cs[r][j] = c_new;
            cn[q] = c_new;
            float s = c_new, ss = c_new * c_new;
#pragma unroll
            for (int off = 16; off > 0; off >>= 1) {
                s  += __shfl_xor_sync(0xffffffffu, s,  off);
                ss += __shfl_xor_sync(0xffffffffu, ss, off);
            }
            if (lane == 0) { redc[r][0][warp & 3] = s; redc[r][1][warp & 3] = ss; }
        }
        __syncthreads();

        float hout[2];
#pragma unroll
        for (int q = 0; q < 2; q++) {
            int r = 2 * rh + q;
            float S  = redc[r][0][0] + redc[r][0][1] + redc[r][0][2] + redc[r][0][3];
            float SS = redc[r][1][0] + redc[r][1][1] + redc[r][1][2] + redc[r][1][3];
            float mu  = S * (1.f / 128.f);
            float var = SS * (1.f / 128.f) - mu * mu;
            float hn = fmaxf((cn[q] - mu) * rsqrtf(var + 1e-12f) * g5 + b5, 0.f) * sigm(og[q]);
            hout[q] = hn;
            o_out[((size_t)(b0 + r) * TT + t) * 128 + j] = hn;
        }
        hs2[j][2 * rh]     = pack2(hout[0], hout[0]);
        hs2[j][2 * rh + 1] = pack2(hout[1], hout[1]);
        __syncthreads();
    }
}

// ---------------- attention ----------------
__global__ __launch_bounds__(128)
void attn_kernel(const float* __restrict__ v1, const float* __restrict__ Wo1, const float* __restrict__ bo1,
                 const float* __restrict__ v2, const float* __restrict__ Wo2, const float* __restrict__ bo2)
{
    int which = blockIdx.y, b = blockIdx.x;
    const float* v  = which ? v2  : v1;
    const float* Wo = which ? Wo2 : Wo1;
    const float* bo = which ? bo2 : bo1;
    const float* o  = g_o[which] + (size_t)b * TT * 128;
    float* a        = g_a[which] + (size_t)b * 512;

    int tid = threadIdx.x, lane = tid & 31, warp = tid >> 5;
    __shared__ float al[TT];
    __shared__ float ctxs[128];

    float4 vv = *(const float4*)&v[lane * 4];
    for (int t = warp; t < TT; t += 4) {
        float4 ov = *(const float4*)&o[t * 128 + lane * 4];
        float p = ov.x * vv.x + ov.y * vv.y + ov.z * vv.z + ov.w * vv.w;
#pragma unroll
        for (int off = 16; off > 0; off >>= 1) p += __shfl_xor_sync(0xffffffffu, p, off);
        if (lane == 0) al[t] = p;
    }
    __syncthreads();

    if (warp == 0) {
        float s0 = (lane < TT)      ? al[lane]      : -1e30f;
        float s1 = (lane + 32 < TT) ? al[lane + 32] : -1e30f;
        float m = fmaxf(s0, s1);
#pragma unroll
        for (int off = 16; off > 0; off >>= 1) m = fmaxf(m, __shfl_xor_sync(0xffffffffu, m, off));
        float e0 = (lane < TT)      ? expf(s0 - m) : 0.f;
        float e1 = (lane + 32 < TT) ? expf(s1 - m) : 0.f;
        float s = e0 + e1;
#pragma unroll
        for (int off = 16; off > 0; off >>= 1) s += __shfl_xor_sync(0xffffffffu, s, off);
        float inv = 1.f / s;
        if (lane < TT)      al[lane]      = e0 * inv;
        if (lane + 32 < TT) al[lane + 32] = e1 * inv;
    }
    __syncthreads();

    float cx = 0.f;
    for (int t = 0; t < TT; t++) cx += al[t] * o[t * 128 + tid];
    ctxs[tid] = cx;
    __syncthreads();

    int c0 = tid * 4;
    float4 accv = *(const float4*)&bo[c0];
#pragma unroll 4
    for (int k = 0; k < 128; k++) {
        float4 w = *(const float4*)&Wo[(size_t)k * 512 + c0];
        float x = ctxs[k];
        accv.x += x * w.x; accv.y += x * w.y; accv.z += x * w.z; accv.w += x * w.w;
    }
    a[c0 + 0] = fmaxf(accv.x, 0.f);
    a[c0 + 1] = fmaxf(accv.y, 0.f);
    a[c0 + 2] = fmaxf(accv.z, 0.f);
    a[c0 + 3] = fmaxf(accv.w, 0.f);
}

// ---------------- head ----------------
__global__ __launch_bounds__(128)
void head_kernel(const float* __restrict__ Wh, const float* __restrict__ bh,
                 const float* __restrict__ Wout, const float* __restrict__ bout,
                 float* __restrict__ out)
{
    int b = blockIdx.x, tid = threadIdx.x;
    int lane = tid & 31, warp = tid >> 5;
    __shared__ float cat[1024];
    __shared__ float hid[512];
    __shared__ float red[2][4];

#pragma unroll
    for (int i = 0; i < 8; i++) {
        int k = tid + 128 * i;
        cat[k] = (k < 512) ? g_a[0][(size_t)b * 512 + k] : g_a[1][(size_t)b * 512 + k - 512];
    }
    __syncthreads();

    int c0 = tid * 4;
    float4 acc = *(const float4*)&bh[c0];
#pragma unroll 4
    for (int k = 0; k < 1024; k++) {
        float4 w = *(const float4*)&Wh[(size_t)k * 512 + c0];
        float x = cat[k];
        acc.x += x * w.x; acc.y += x * w.y; acc.z += x * w.z; acc.w += x * w.w;
    }
    hid[c0 + 0] = fmaxf(acc.x, 0.f);
    hid[c0 + 1] = fmaxf(acc.y, 0.f);
    hid[c0 + 2] = fmaxf(acc.z, 0.f);
    hid[c0 + 3] = fmaxf(acc.w, 0.f);
    __syncthreads();

    float p0 = 0.f, p1 = 0.f;
#pragma unroll
    for (int i = 0; i < 4; i++) {
        float h = hid[c0 + i];
        p0 += h * Wout[(c0 + i) * 2 + 0];
        p1 += h * Wout[(c0 + i) * 2 + 1];
    }
#pragma unroll
    for (int off = 16; off > 0; off >>= 1) {
        p0 += __shfl_xor_sync(0xffffffffu, p0, off);
        p1 += __shfl_xor_sync(0xffffffffu, p1, off);
    }
    if (lane == 0) { red[0][warp] = p0; red[1][warp] = p1; }
    __syncthreads();
    if (tid == 0) {
        out[b * 2 + 0] = red[0][0] + red[0][1] + red[0][2] + red[0][3] + bout[0];
        out[b * 2 + 1] = red[1][0] + red[1][1] + red[1][2] + red[1][3] + bout[1];
    }
}

// ---------------- host: tensor maps + launch ----------------
typedef CUresult (*PFN_tmapEnc)(CUtensorMap*, CUtensorMapDataType, cuuint32_t, void*,
                                const cuuint64_t*, const cuuint64_t*, const cuuint32_t*,
                                const cuuint32_t*, CUtensorMapInterleave, CUtensorMapSwizzle,
                                CUtensorMapL2promotion, CUtensorMapFloatOOBfill);

static CUtensorMap s_maps[8];   // Ah0 Al0 Bh0 Bl0 Ah1 Al1 Bh1 Bl1
static int s_init = 0;

static void make_map(PFN_tmapEnc fn, CUtensorMap* m, void* ptr,
                     unsigned long long rows, unsigned boxRows)
{
    cuuint64_t dims[2]    = {KPAD, rows};
    cuuint64_t strides[1] = {KPAD * 2ULL};
    cuuint32_t box[2]     = {64, boxRows};
    cuuint32_t es[2]      = {1, 1};
    fn(m, CU_TENSOR_MAP_DATA_TYPE_BFLOAT16, 2, ptr, dims, strides, box, es,
       CU_TENSOR_MAP_INTERLEAVE_NONE, CU_TENSOR_MAP_SWIZZLE_128B,
       CU_TENSOR_MAP_L2_PROMOTION_L2_128B, CU_TENSOR_MAP_FLOAT_OOB_FILL_NONE);
}

extern "C" void kernel_launch(void* const* d_in, const int* in_sizes, int n_in,
                              void* d_out, int out_size)
{
    const float* x1     = (const float*)d_in[0];
    const float* x2     = (const float*)d_in[1];
    const float* embed1 = (const float*)d_in[2];
    const float* embed2 = (const float*)d_in[3];
    const float* Wl1    = (const float*)d_in[4];
    const float* Wl2    = (const float*)d_in[5];
    const float* lng1   = (const float*)d_in[6];
    const float* lnb1   = (const float*)d_in[7];
    const float* lng2   = (const float*)d_in[8];
    const float* lnb2   = (const float*)d_in[9];
    const float* av1    = (const float*)d_in[10];
    const float* aWo1   = (const float*)d_in[11];
    const float* abo1   = (const float*)d_in[12];
    const float* av2    = (const float*)d_in[13];
    const float* aWo2   = (const float*)d_in[14];
    const float* abo2   = (const float*)d_in[15];
    const float* Wh     = (const float*)d_in[16];
    const float* bh     = (const float*)d_in[17];
    const float* Wout   = (const float*)d_in[18];
    const float* bout   = (const float*)d_in[19];
    float* out = (float*)d_out;

    if (!s_init) {
        cudaFuncSetAttribute(hmma_kernel,
                             cudaFuncAttributeMaxDynamicSharedMemorySize, SMEM_H);
        PFN_tmapEnc fn = nullptr;
        cudaDriverEntryPointQueryResult qr;
        cudaGetDriverEntryPoint("cuTensorMapEncodeTiled", (void**)&fn,
                                cudaEnableDefault, &qr);
        void *pxh, *pxl, *peh, *pel;
        cudaGetSymbolAddress(&pxh, g_xhi);
        cudaGetSymbolAddress(&pxl, g_xlo);
        cudaGetSymbolAddress(&peh, g_ehT);
        cudaGetSymbolAddress(&pel, g_elT);
        size_t xs = (size_t)MROWS * KPAD * 2;
        size_t es = (size_t)NPAD * KPAD * 2;
        make_map(fn, &s_maps[0], (char*)pxh,        MROWS, 64);
        make_map(fn, &s_maps[1], (char*)pxl,        MROWS, 64);
        make_map(fn, &s_maps[2], (char*)peh,        NPAD,  160);
        make_map(fn, &s_maps[3], (char*)pel,        NPAD,  160);
        make_map(fn, &s_maps[4], (char*)pxh + xs,   MROWS, 64);
        make_map(fn, &s_maps[5], (char*)pxl + xs,   MROWS, 64);
        make_map(fn, &s_maps[6], (char*)peh + es,   NPAD,  160);
        make_map(fn, &s_maps[7], (char*)pel + es,   NPAD,  160);
        s_init = 1;
    }

    // 0,1) bf16 hi/lo splits (z merged into grid.y)
    convE_kernel<<<dim3((NPAD*KPAD/8 + 255)/256, 2), 256>>>(embed1, embed2);
    convx_kernel<<<dim3((int)((size_t)MROWS*KPAD/8/256), 2), 256>>>(x1, x2);

    // 2) e-partials = x @ embed via HMMA + TMA, merged grid (n*kz, m, z)
    hmma_kernel<<<dim3(4, 92, 2), 256, SMEM_H>>>(
        s_maps[0], s_maps[1], s_maps[2], s_maps[3],
        s_maps[4], s_maps[5], s_maps[6], s_maps[7]);

    // 3) xz = (p0+p1) @ W_lstm[0:300,:]
    gemm_kernel<<<dim3(4, 46, 2), 256>>>(Wl1, Wl2);

    // 4) recurrence
    lstm_kernel<<<dim3(32, 2), 256>>>(Wl1, Wl2, lng1, lnb1, lng2, lnb2);
    // 5) attention
    attn_kernel<<<dim3(128, 2), 128>>>(av1, aWo1, abo1, av2, aWo2, abo2);
    // 6) head
    head_kernel<<<128, 128>>>(Wh, bh, Wout, bout, out);
}

// round 16
// speedup vs baseline: 3.9391x; 1.0779x over previous
#include <cuda_runtime.h>
#include <cuda.h>
#include <cuda_bf16.h>
#include <math.h>
#include <stdint.h>

// ---------------- scratch (static device memory; no allocations) ----------------
#define BB 128
#define TT 46
#define VV 8150
#define EE 300
#define HH 128
#define MROWS (BB*TT)   // 5888
#define KPAD 8192
#define NPAD 384
#define XK   320        // padded K for xz HMMA (300 -> 320)

__device__ float g_ep[2][2][MROWS*EE];   // split-K partial embeddings [z][kz][5888,300]
__device__ float g_xz[2][MROWS*512];     // x-part of gates
__device__ float g_o [2][MROWS*HH];      // lstm outputs
__device__ float g_a [2][BB*512];        // attention outputs

// bf16 split operands (embedding GEMM)
__device__ __nv_bfloat16 g_xhi[2][(size_t)MROWS*KPAD];
__device__ __nv_bfloat16 g_xlo[2][(size_t)MROWS*KPAD];
__device__ __nv_bfloat16 g_ehT[2][(size_t)NPAD*KPAD];
__device__ __nv_bfloat16 g_elT[2][(size_t)NPAD*KPAD];

// bf16 split operands (xz GEMM)
__device__ __nv_bfloat16 g_ehi[2][(size_t)MROWS*XK];
__device__ __nv_bfloat16 g_elo[2][(size_t)MROWS*XK];
__device__ __nv_bfloat16 g_wh [2][(size_t)512*XK];
__device__ __nv_bfloat16 g_wl [2][(size_t)512*XK];

// ---------------- helpers ----------------
__device__ __forceinline__ unsigned long long ffma2(unsigned long long a,
                                                    unsigned long long b,
                                                    unsigned long long c) {
    unsigned long long d;
    asm("fma.rn.f32x2 %0, %1, %2, %3;" : "=l"(d) : "l"(a), "l"(b), "l"(c));
    return d;
}
__device__ __forceinline__ unsigned long long pack2(float x, float y) {
    unsigned long long d;
    asm("mov.b64 %0, {%1, %2};" : "=l"(d) : "r"(__float_as_uint(x)), "r"(__float_as_uint(y)));
    return d;
}
__device__ __forceinline__ float2 unpack2(unsigned long long v) {
    unsigned int lo, hi;
    asm("mov.b64 {%0, %1}, %2;" : "=r"(lo), "=r"(hi) : "l"(v));
    return make_float2(__uint_as_float(lo), __uint_as_float(hi));
}
__device__ __forceinline__ float sigm(float x) { return 1.0f / (1.0f + expf(-x)); }

__device__ __forceinline__ uint32_t smem_u32(const void* p) {
    uint32_t a;
    asm("{ .reg .u64 t; cvta.to.shared.u64 t, %1; cvt.u32.u64 %0, t; }" : "=r"(a) : "l"(p));
    return a;
}

#define MBAR_INIT(a, cnt) asm volatile("mbarrier.init.shared.b64 [%0], %1;" :: "r"(a), "r"(cnt) : "memory")
#define MBAR_EXPECT_TX(a, b) asm volatile("mbarrier.arrive.expect_tx.shared.b64 _, [%0], %1;" :: "r"(a), "r"(b) : "memory")
#define MBAR_WAIT(a, ph) do { \
    uint32_t _m = (a), _p = (ph), _d; \
    asm volatile("{ .reg .pred p; mbarrier.try_wait.parity.acquire.cta.shared::cta.b64 p, [%1], %2; selp.b32 %0,1,0,p; }" \
        : "=r"(_d) : "r"(_m), "r"(_p) : "memory"); \
    if (!_d) { \
        asm volatile("{ .reg .pred P1; WL_%=: mbarrier.try_wait.parity.acquire.cta.shared::cta.b64 P1, [%0], %1, 0x989680; @P1 bra.uni WD_%=; bra.uni WL_%=; WD_%=: }" \
            :: "r"(_m), "r"(_p) : "memory"); \
    } } while (0)

__device__ __forceinline__ void tma2d(uint32_t smem, const CUtensorMap* m,
                                      int x, int y, uint32_t mbar) {
    asm volatile(
        "cp.async.bulk.tensor.2d.shared::cta.global.tile.mbarrier::complete_tx::bytes "
        "[%0], [%1, {%2, %3}], [%4];"
        :: "r"(smem), "l"(m), "r"(x), "r"(y), "r"(mbar) : "memory");
}

__device__ __forceinline__ void ldsm4(uint32_t* r, uint32_t a) {
    asm volatile("ldmatrix.sync.aligned.m8n8.x4.shared.b16 {%0,%1,%2,%3}, [%4];"
        : "=r"(r[0]), "=r"(r[1]), "=r"(r[2]), "=r"(r[3]) : "r"(a));
}
__device__ __forceinline__ void ldsm2(uint32_t* r, uint32_t a) {
    asm volatile("ldmatrix.sync.aligned.m8n8.x2.shared.b16 {%0,%1}, [%2];"
        : "=r"(r[0]), "=r"(r[1]) : "r"(a));
}
__device__ __forceinline__ void mma16816(float* d, const uint32_t* a, const uint32_t* b) {
    asm volatile("mma.sync.aligned.m16n8k16.row.col.f32.bf16.bf16.f32 "
        "{%0,%1,%2,%3}, {%4,%5,%6,%7}, {%8,%9}, {%0,%1,%2,%3};"
        : "+f"(d[0]), "+f"(d[1]), "+f"(d[2]), "+f"(d[3])
        : "r"(a[0]), "r"(a[1]), "r"(a[2]), "r"(a[3]), "r"(b[0]), "r"(b[1]));
}

// ---------------- conversion kernels ----------------
__global__ __launch_bounds__(256)
void convx_kernel(const float* __restrict__ x0, const float* __restrict__ x1)
{
    int z = blockIdx.y;
    const float* x = z ? x1 : x0;
    size_t idx = (size_t)blockIdx.x * 256 + threadIdx.x;
    int row = (int)(idx >> 10);
    int kk  = (int)(idx & 1023) << 3;
    __align__(16) __nv_bfloat16 h[8], l[8];
    const float* xr = x + (size_t)row * VV;
#pragma unroll
    for (int j2 = 0; j2 < 4; j2++) {
        int k = kk + j2 * 2;
        float2 v2 = make_float2(0.f, 0.f);
        if (k + 1 < VV) v2 = *(const float2*)(xr + k);   // row*VV even, k even -> 8B aligned
        __nv_bfloat16 hb0 = __float2bfloat16(v2.x);
        __nv_bfloat16 hb1 = __float2bfloat16(v2.y);
        h[j2*2]   = hb0; l[j2*2]   = __float2bfloat16(v2.x - __bfloat162float(hb0));
        h[j2*2+1] = hb1; l[j2*2+1] = __float2bfloat16(v2.y - __bfloat162float(hb1));
    }
    size_t o = (size_t)row * KPAD + kk;
    *(uint4*)&g_xhi[z][o] = *(uint4*)h;
    *(uint4*)&g_xlo[z][o] = *(uint4*)l;
}

__global__ __launch_bounds__(256)
void convE_kernel(const float* __restrict__ e0, const float* __restrict__ e1)
{
    int z = blockIdx.y;
    const float* embed = z ? e1 : e0;
    size_t idx = (size_t)blockIdx.x * 256 + threadIdx.x;
    int n  = (int)(idx >> 10);
    int kk = (int)(idx & 1023) << 3;
    __align__(16) __nv_bfloat16 h[8], l[8];
#pragma unroll
    for (int j = 0; j < 8; j++) {
        int k = kk + j;
        float v = (n < EE && k < VV) ? embed[(size_t)k * EE + n] : 0.f;
        __nv_bfloat16 hb = __float2bfloat16(v);
        h[j] = hb;
        l[j] = __float2bfloat16(v - __bfloat162float(hb));
    }
    size_t o = (size_t)n * KPAD + kk;
    *(uint4*)&g_ehT[z][o] = *(uint4*)h;
    *(uint4*)&g_elT[z][o] = *(uint4*)l;
}

// Wx^T -> bf16 hi/lo [512, XK] ;  g_w?[n*XK + k] = W[k*512 + n], k<300
__global__ __launch_bounds__(256)
void convW_kernel(const float* __restrict__ W1, const float* __restrict__ W2)
{
    int z = blockIdx.y;
    const float* W = z ? W2 : W1;
    size_t idx = (size_t)blockIdx.x * 256 + threadIdx.x;
    int n  = (int)(idx / 40);          // 40 segments of 8 -> 320 cols
    int kk = (int)(idx % 40) << 3;
    __align__(16) __nv_bfloat16 h[8], l[8];
#pragma unroll
    for (int j = 0; j < 8; j++) {
        int k = kk + j;
        float v = (k < EE) ? W[(size_t)k * 512 + n] : 0.f;
        __nv_bfloat16 hb = __float2bfloat16(v);
        h[j] = hb;
        l[j] = __float2bfloat16(v - __bfloat162float(hb));
    }
    size_t o = (size_t)n * XK + kk;
    *(uint4*)&g_wh[z][o] = *(uint4*)h;
    *(uint4*)&g_wl[z][o] = *(uint4*)l;
}

// e = p0+p1 -> bf16 hi/lo [5888, XK]
__global__ __launch_bounds__(256)
void conv_e_kernel()
{
    int z = blockIdx.y;
    size_t idx = (size_t)blockIdx.x * 256 + threadIdx.x;
    int row = (int)(idx / 40);
    int kk  = (int)(idx % 40) << 3;
    const float* p0 = g_ep[z][0] + (size_t)row * EE;
    const float* p1 = g_ep[z][1] + (size_t)row * EE;
    __align__(16) __nv_bfloat16 h[8], l[8];
#pragma unroll
    for (int j2 = 0; j2 < 4; j2++) {
        int k = kk + j2 * 2;
        float2 v2 = make_float2(0.f, 0.f);
        if (k + 1 < EE) {                           // 300 even, k even -> no straddle
            float2 a = *(const float2*)(p0 + k);
            float2 b = *(const float2*)(p1 + k);
            v2.x = a.x + b.x; v2.y = a.y + b.y;
        }
        __nv_bfloat16 hb0 = __float2bfloat16(v2.x);
        __nv_bfloat16 hb1 = __float2bfloat16(v2.y);
        h[j2*2]   = hb0; l[j2*2]   = __float2bfloat16(v2.x - __bfloat162float(hb0));
        h[j2*2+1] = hb1; l[j2*2+1] = __float2bfloat16(v2.y - __bfloat162float(hb1));
    }
    size_t o = (size_t)row * XK + kk;
    *(uint4*)&g_ehi[z][o] = *(uint4*)h;
    *(uint4*)&g_elo[z][o] = *(uint4*)l;
}

// ---------------- HMMA bf16-split GEMM with TMA (known-good config) ----------------
#define STG_B   57344
#define SMEM_H  (2*STG_B + 64)
#define NCHUNK  64

__device__ __forceinline__ void hmma_issue(uint32_t sb, int s, int k0, int m0, int n0,
    const CUtensorMap* pAh, const CUtensorMap* pAl,
    const CUtensorMap* pBh, const CUtensorMap* pBl)
{
    uint32_t mb = sb + 2*STG_B + 8*s;
    uint32_t base = sb + s*STG_B;
    MBAR_EXPECT_TX(mb, STG_B);
    tma2d(base,         pAh, k0, m0, mb);
    tma2d(base + 8192,  pAl, k0, m0, mb);
    tma2d(base + 16384, pBh, k0, n0, mb);
    tma2d(base + 36864, pBl, k0, n0, mb);
}

__global__ __launch_bounds__(256, 2)
void hmma_kernel(
    const __grid_constant__ CUtensorMap mAh0, const __grid_constant__ CUtensorMap mAl0,
    const __grid_constant__ CUtensorMap mBh0, const __grid_constant__ CUtensorMap mBl0,
    const __grid_constant__ CUtensorMap mAh1, const __grid_constant__ CUtensorMap mAl1,
    const __grid_constant__ CUtensorMap mBh1, const __grid_constant__ CUtensorMap mBl1)
{
    extern __shared__ __align__(1024) char smem[];
    uint32_t sb = smem_u32(smem);
    int tid = threadIdx.x, lane = tid & 31, wid = tid >> 5;
    int z  = blockIdx.z;
    int kz = blockIdx.x & 1;
    int n0 = (blockIdx.x >> 1) * 160;
    int m0 = blockIdx.y * 64;
    int wm = wid & 1, wn = wid >> 1;

    const CUtensorMap* pAh = z ? &mAh1 : &mAh0;
    const CUtensorMap* pAl = z ? &mAl1 : &mAl0;
    const CUtensorMap* pBh = z ? &mBh1 : &mBh0;
    const CUtensorMap* pBl = z ? &mBl1 : &mBl0;

    if (tid == 0) { MBAR_INIT(sb + 2*STG_B, 1); MBAR_INIT(sb + 2*STG_B + 8, 1); }
    __syncthreads();

    int kbase = kz * 4096;
    if (tid == 0) {
        hmma_issue(sb, 0, kbase,      m0, n0, pAh, pAl, pBh, pBl);
        hmma_issue(sb, 1, kbase + 64, m0, n0, pAh, pAl, pBh, pBl);
    }

    int u0 = lane >> 4;
    int u1 = (lane >> 3) & 1;
    int aoff[2], axr[2];
#pragma unroll
    for (int mf = 0; mf < 2; mf++) {
        int mr = wm * 32 + mf * 16 + (lane & 15);
        aoff[mf] = mr * 128;
        axr[mf]  = mr & 7;
    }
    int noff[5], nxr[5];
#pragma unroll
    for (int nf = 0; nf < 5; nf++) {
        int nr = wn * 40 + nf * 8 + (lane & 7);
        noff[nf] = nr * 128;
        nxr[nf]  = nr & 7;
    }

    float acc[2][5][4];
#pragma unroll
    for (int mf = 0; mf < 2; mf++)
#pragma unroll
        for (int nf = 0; nf < 5; nf++)
#pragma unroll
            for (int q = 0; q < 4; q++) acc[mf][nf][q] = 0.f;

    int ph0 = 0, ph1 = 0;
    for (int c = 0; c < NCHUNK; c++) {
        int s = c & 1;
        if (s == 0) { MBAR_WAIT(sb + 2*STG_B, ph0); ph0 ^= 1; }
        else        { MBAR_WAIT(sb + 2*STG_B + 8, ph1); ph1 ^= 1; }
        uint32_t base = sb + s * STG_B;

#pragma unroll
        for (int ks = 0; ks < 4; ks++) {
            uint32_t a[2][4], al[2][4], bh[5][2], bl[5][2];
#pragma unroll
            for (int mf = 0; mf < 2; mf++)
                ldsm4(a[mf], base + aoff[mf] + ((((ks << 1) + u0) ^ axr[mf]) << 4));
#pragma unroll
            for (int nf = 0; nf < 5; nf++)
                ldsm2(bh[nf], base + 16384 + noff[nf] + ((((ks << 1) + u1) ^ nxr[nf]) << 4));
#pragma unroll
            for (int mf = 0; mf < 2; mf++)
#pragma unroll
                for (int nf = 0; nf < 5; nf++) mma16816(acc[mf][nf], a[mf], bh[nf]);
#pragma unroll
            for (int mf = 0; mf < 2; mf++)
                ldsm4(al[mf], base + 8192 + aoff[mf] + ((((ks << 1) + u0) ^ axr[mf]) << 4));
#pragma unroll
            for (int mf = 0; mf < 2; mf++)
#pragma unroll
                for (int nf = 0; nf < 5; nf++) mma16816(acc[mf][nf], al[mf], bh[nf]);
#pragma unroll
            for (int nf = 0; nf < 5; nf++)
                ldsm2(bl[nf], base + 36864 + noff[nf] + ((((ks << 1) + u1) ^ nxr[nf]) << 4));
#pragma unroll
            for (int mf = 0; mf < 2; mf++)
#pragma unroll
                for (int nf = 0; nf < 5; nf++) mma16816(acc[mf][nf], a[mf], bl[nf]);
        }
        __syncthreads();
        if (c + 2 < NCHUNK && tid == 0)
            hmma_issue(sb, s, kbase + (c + 2) * 64, m0, n0, pAh, pAl, pBh, pBl);
    }

    float* C = g_ep[z][kz];
#pragma unroll
    for (int mf = 0; mf < 2; mf++) {
        int r0 = m0 + wm * 32 + mf * 16 + (lane >> 2);
#pragma unroll
        for (int nf = 0; nf < 5; nf++) {
            int col = n0 + wn * 40 + nf * 8 + (lane & 3) * 2;
            if (col < EE) {
                *(float2*)&C[(size_t)r0 * EE + col]       = make_float2(acc[mf][nf][0], acc[mf][nf][1]);
                *(float2*)&C[(size_t)(r0 + 8) * EE + col] = make_float2(acc[mf][nf][2], acc[mf][nf][3]);
            }
        }
    }
}

// ---------------- HMMA xz GEMM: xz = e @ Wx via bf16 split ----------------
// CTA: M=64, N=128, K=320 in 5 chunks of 64.
// Stage: Ah 8K | Al 8K | Bh 16K | Bl 16K = 48K; 2 stages = 96K.
#define STG_X   49152
#define SMEM_X  (2*STG_X + 64)
#define XCH     5

__device__ __forceinline__ void xz_issue(uint32_t sb, int s, int k0, int m0, int n0,
    const CUtensorMap* pAh, const CUtensorMap* pAl,
    const CUtensorMap* pBh, const CUtensorMap* pBl)
{
    uint32_t mb = sb + 2*STG_X + 8*s;
    uint32_t base = sb + s*STG_X;
    MBAR_EXPECT_TX(mb, STG_X);
    tma2d(base,         pAh, k0, m0, mb);
    tma2d(base + 8192,  pAl, k0, m0, mb);
    tma2d(base + 16384, pBh, k0, n0, mb);
    tma2d(base + 32768, pBl, k0, n0, mb);
}

__global__ __launch_bounds__(256, 2)
void hmma_xz_kernel(
    const __grid_constant__ CUtensorMap mAh0, const __grid_constant__ CUtensorMap mAl0,
    const __grid_constant__ CUtensorMap mBh0, const __grid_constant__ CUtensorMap mBl0,
    const __grid_constant__ CUtensorMap mAh1, const __grid_constant__ CUtensorMap mAl1,
    const __grid_constant__ CUtensorMap mBh1, const __grid_constant__ CUtensorMap mBl1)
{
    extern __shared__ __align__(1024) char smem[];
    uint32_t sb = smem_u32(smem);
    int tid = threadIdx.x, lane = tid & 31, wid = tid >> 5;
    int z  = blockIdx.z;
    int n0 = blockIdx.x * 128;
    int m0 = blockIdx.y * 64;
    int wm = wid & 1, wn = wid >> 1;

    const CUtensorMap* pAh = z ? &mAh1 : &mAh0;
    const CUtensorMap* pAl = z ? &mAl1 : &mAl0;
    const CUtensorMap* pBh = z ? &mBh1 : &mBh0;
    const CUtensorMap* pBl = z ? &mBl1 : &mBl0;

    if (tid == 0) { MBAR_INIT(sb + 2*STG_X, 1); MBAR_INIT(sb + 2*STG_X + 8, 1); }
    __syncthreads();

    if (tid == 0) {
        xz_issue(sb, 0, 0,  m0, n0, pAh, pAl, pBh, pBl);
        xz_issue(sb, 1, 64, m0, n0, pAh, pAl, pBh, pBl);
    }

    int u0 = lane >> 4;
    int u1 = (lane >> 3) & 1;
    int aoff[2], axr[2];
#pragma unroll
    for (int mf = 0; mf < 2; mf++) {
        int mr = wm * 32 + mf * 16 + (lane & 15);
        aoff[mf] = mr * 128;
        axr[mf]  = mr & 7;
    }
    int noff[4], nxr[4];
#pragma unroll
    for (int nf = 0; nf < 4; nf++) {
        int nr = wn * 32 + nf * 8 + (lane & 7);
        noff[nf] = nr * 128;
        nxr[nf]  = nr & 7;
    }

    float acc[2][4][4];
#pragma unroll
    for (int mf = 0; mf < 2; mf++)
#pragma unroll
        for (int nf = 0; nf < 4; nf++)
#pragma unroll
            for (int q = 0; q < 4; q++) acc[mf][nf][q] = 0.f;

    int ph0 = 0, ph1 = 0;
    for (int c = 0; c < XCH; c++) {
        int s = c & 1;
        if (s == 0) { MBAR_WAIT(sb + 2*STG_X, ph0); ph0 ^= 1; }
        else        { MBAR_WAIT(sb + 2*STG_X + 8, ph1); ph1 ^= 1; }
        uint32_t base = sb + s * STG_X;

#pragma unroll
        for (int ks = 0; ks < 4; ks++) {
            uint32_t a[2][4], al[2][4], bh[4][2], bl[4][2];
#pragma unroll
            for (int mf = 0; mf < 2; mf++)
                ldsm4(a[mf], base + aoff[mf] + ((((ks << 1) + u0) ^ axr[mf]) << 4));
#pragma unroll
            for (int nf = 0; nf < 4; nf++)
                ldsm2(bh[nf], base + 16384 + noff[nf] + ((((ks << 1) + u1) ^ nxr[nf]) << 4));
#pragma unroll
            for (int mf = 0; mf < 2; mf++)
#pragma unroll
                for (int nf = 0; nf < 4; nf++) mma16816(acc[mf][nf], a[mf], bh[nf]);
#pragma unroll
            for (int mf = 0; mf < 2; mf++)
                ldsm4(al[mf], base + 8192 + aoff[mf] + ((((ks << 1) + u0) ^ axr[mf]) << 4));
#pragma unroll
            for (int mf = 0; mf < 2; mf++)
#pragma unroll
                for (int nf = 0; nf < 4; nf++) mma16816(acc[mf][nf], al[mf], bh[nf]);
#pragma unroll
            for (int nf = 0; nf < 4; nf++)
                ldsm2(bl[nf], base + 32768 + noff[nf] + ((((ks << 1) + u1) ^ nxr[nf]) << 4));
#pragma unroll
            for (int mf = 0; mf < 2; mf++)
#pragma unroll
                for (int nf = 0; nf < 4; nf++) mma16816(acc[mf][nf], a[mf], bl[nf]);
        }
        __syncthreads();
        if (c + 2 < XCH && tid == 0)
            xz_issue(sb, s, (c + 2) * 64, m0, n0, pAh, pAl, pBh, pBl);
    }

    float* C = g_xz[z];
#pragma unroll
    for (int mf = 0; mf < 2; mf++) {
        int r0 = m0 + wm * 32 + mf * 16 + (lane >> 2);
#pragma unroll
        for (int nf = 0; nf < 4; nf++) {
            int col = n0 + wn * 32 + nf * 8 + (lane & 3) * 2;
            *(float2*)&C[(size_t)r0 * 512 + col]       = make_float2(acc[mf][nf][0], acc[mf][nf][1]);
            *(float2*)&C[(size_t)(r0 + 8) * 512 + col] = make_float2(acc[mf][nf][2], acc[mf][nf][3]);
        }
    }
}

// ---------------- LSTM recurrent kernel (unchanged, known-good) ----------------
__global__ __launch_bounds__(256)
void lstm_kernel(const float* __restrict__ W1, const float* __restrict__ W2,
                 const float* __restrict__ lng1, const float* __restrict__ lnb1,
                 const float* __restrict__ lng2, const float* __restrict__ lnb2)
{
    int which = blockIdx.y;
    const float* Wh  = (which ? W2 : W1) + 300 * 512;
    const float* lng = which ? lng2 : lng1;
    const float* lnb = which ? lnb2 : lnb1;
    const float* xz  = g_xz[which];
    float* o_out     = g_o[which];

    int b0  = blockIdx.x * 4;
    int tid = threadIdx.x;
    int lane = tid & 31, warp = tid >> 5;

    __shared__ __align__(16) unsigned long long hs2[128][4];
    __shared__ float cs[4][128];
    __shared__ float zs[4][512];
    __shared__ float redg[4][4][2][2];
    __shared__ float redc[4][2][4];

    if (tid < 128) {
#pragma unroll
        for (int r = 0; r < 4; r++) { hs2[tid][r] = 0ULL; cs[r][tid] = 0.f; }
    }
    __syncthreads();

    int c0 = tid * 2;
    int gate = tid >> 6;
    int ghalf = (tid >> 5) & 1;
    int jg = c0 & 127;
    float gg0 = lng[gate * 128 + jg],     gg1 = lng[gate * 128 + jg + 1];
    float gb0 = lnb[gate * 128 + jg],     gb1 = lnb[gate * 128 + jg + 1];
    int j = tid & 127, rh = tid >> 7;
    float g5 = lng[4 * 128 + j], b5 = lnb[4 * 128 + j];

    for (int t = 0; t < TT; t++) {
        unsigned long long acc[4];
#pragma unroll
        for (int r = 0; r < 4; r++)
            acc[r] = *(const unsigned long long*)&xz[((size_t)(b0 + r) * TT + t) * 512 + c0];
#pragma unroll 4
        for (int k = 0; k < 128; k++) {
            unsigned long long w = *(const unsigned long long*)&Wh[(size_t)k * 512 + c0];
            ulonglong2 h01 = *(const ulonglong2*)&hs2[k][0];
            ulonglong2 h23 = *(const ulonglong2*)&hs2[k][2];
            acc[0] = ffma2(h01.x, w, acc[0]);
            acc[1] = ffma2(h01.y, w, acc[1]);
            acc[2] = ffma2(h23.x, w, acc[2]);
            acc[3] = ffma2(h23.y, w, acc[3]);
        }

#pragma unroll
        for (int r = 0; r < 4; r++) {
            float2 p = unpack2(acc[r]);
            float s  = p.x + p.y;
            float ss = p.x * p.x + p.y * p.y;
#pragma unroll
            for (int off = 16; off > 0; off >>= 1) {
                s  += __shfl_xor_sync(0xffffffffu, s,  off);
                ss += __shfl_xor_sync(0xffffffffu, ss, off);
            }
            if (lane == 0) { redg[r][gate][ghalf][0] = s; redg[r][gate][ghalf][1] = ss; }
        }
        __syncthreads();
#pragma unroll
        for (int r = 0; r < 4; r++) {
            float S  = redg[r][gate][0][0] + redg[r][gate][1][0];
            float SS = redg[r][gate][0][1] + redg[r][gate][1][1];
            float mu  = S * (1.f / 128.f);
            float var = SS * (1.f / 128.f) - mu * mu;
            float inv = rsqrtf(var + 1e-12f);
            float2 p = unpack2(acc[r]);
            zs[r][c0]     = (p.x - mu) * inv * gg0 + gb0;
            zs[r][c0 + 1] = (p.y - mu) * inv * gg1 + gb1;
        }
        __syncthreads();

        float cn[2], og[2];
#pragma unroll
        for (int q = 0; q < 2; q++) {
            int r = 2 * rh + q;
            float ig = zs[r][j];
            float jj = zs[r][128 + j];
            float fg = zs[r][256 + j];
            og[q]    = zs[r][384 + j];
            float c_new = cs[r][j] * sigm(fg + 1.0f) + sigm(ig) * fmaxf(jj, 0.f);
            cs[r][j] = c_new;
            cn[q] = c_new;
            float s = c_new, ss = c_new * c_new;
#pragma unroll
            for (int off = 16; off > 0; off >>= 1) {
                s  += __shfl_xor_sync(0xffffffffu, s,  off);
                ss += __shfl_xor_sync(0xffffffffu, ss, off);
            }
            if (lane == 0) { redc[r][0][warp & 3] = s; redc[r][1][warp & 3] = ss; }
        }
        __syncthreads();

        float hout[2];
#pragma unroll
        for (int q = 0; q < 2; q++) {
            int r = 2 * rh + q;
            float S  = redc[r][0][0] + redc[r][0][1] + redc[r][0][2] + redc[r][0][3];
            float SS = redc[r][1][0] + redc[r][1][1] + redc[r][1][2] + redc[r][1][3];
            float mu  = S * (1.f / 128.f);
            float var = SS * (1.f / 128.f) - mu * mu;
            float hn = fmaxf((cn[q] - mu) * rsqrtf(var + 1e-12f) * g5 + b5, 0.f) * sigm(og[q]);
            hout[q] = hn;
            o_out[((size_t)(b0 + r) * TT + t) * 128 + j] = hn;
        }
        hs2[j][2 * rh]     = pack2(hout[0], hout[0]);
        hs2[j][2 * rh + 1] = pack2(hout[1], hout[1]);
        __syncthreads();
    }
}

// ---------------- attention (unchanged) ----------------
__global__ __launch_bounds__(128)
void attn_kernel(const float* __restrict__ v1, const float* __restrict__ Wo1, const float* __restrict__ bo1,
                 const float* __restrict__ v2, const float* __restrict__ Wo2, const float* __restrict__ bo2)
{
    int which = blockIdx.y, b = blockIdx.x;
    const float* v  = which ? v2  : v1;
    const float* Wo = which ? Wo2 : Wo1;
    const float* bo = which ? bo2 : bo1;
    const float* o  = g_o[which] + (size_t)b * TT * 128;
    float* a        = g_a[which] + (size_t)b * 512;

    int tid = threadIdx.x, lane = tid & 31, warp = tid >> 5;
    __shared__ float al[TT];
    __shared__ float ctxs[128];

    float4 vv = *(const float4*)&v[lane * 4];
    for (int t = warp; t < TT; t += 4) {
        float4 ov = *(const float4*)&o[t * 128 + lane * 4];
        float p = ov.x * vv.x + ov.y * vv.y + ov.z * vv.z + ov.w * vv.w;
#pragma unroll
        for (int off = 16; off > 0; off >>= 1) p += __shfl_xor_sync(0xffffffffu, p, off);
        if (lane == 0) al[t] = p;
    }
    __syncthreads();

    if (warp == 0) {
        float s0 = (lane < TT)      ? al[lane]      : -1e30f;
        float s1 = (lane + 32 < TT) ? al[lane + 32] : -1e30f;
        float m = fmaxf(s0, s1);
#pragma unroll
        for (int off = 16; off > 0; off >>= 1) m = fmaxf(m, __shfl_xor_sync(0xffffffffu, m, off));
        float e0 = (lane < TT)      ? expf(s0 - m) : 0.f;
        float e1 = (lane + 32 < TT) ? expf(s1 - m) : 0.f;
        float s = e0 + e1;
#pragma unroll
        for (int off = 16; off > 0; off >>= 1) s += __shfl_xor_sync(0xffffffffu, s, off);
        float inv = 1.f / s;
        if (lane < TT)      al[lane]      = e0 * inv;
        if (lane + 32 < TT) al[lane + 32] = e1 * inv;
    }
    __syncthreads();

    float cx = 0.f;
    for (int t = 0; t < TT; t++) cx += al[t] * o[t * 128 + tid];
    ctxs[tid] = cx;
    __syncthreads();

    int c0 = tid * 4;
    float4 accv = *(const float4*)&bo[c0];
#pragma unroll 4
    for (int k = 0; k < 128; k++) {
        float4 w = *(const float4*)&Wo[(size_t)k * 512 + c0];
        float x = ctxs[k];
        accv.x += x * w.x; accv.y += x * w.y; accv.z += x * w.z; accv.w += x * w.w;
    }
    a[c0 + 0] = fmaxf(accv.x, 0.f);
    a[c0 + 1] = fmaxf(accv.y, 0.f);
    a[c0 + 2] = fmaxf(accv.z, 0.f);
    a[c0 + 3] = fmaxf(accv.w, 0.f);
}

// ---------------- head (unchanged) ----------------
__global__ __launch_bounds__(128)
void head_kernel(const float* __restrict__ Wh, const float* __restrict__ bh,
                 const float* __restrict__ Wout, const float* __restrict__ bout,
                 float* __restrict__ out)
{
    int b = blockIdx.x, tid = threadIdx.x;
    int lane = tid & 31, warp = tid >> 5;
    __shared__ float cat[1024];
    __shared__ float hid[512];
    __shared__ float red[2][4];

#pragma unroll
    for (int i = 0; i < 8; i++) {
        int k = tid + 128 * i;
        cat[k] = (k < 512) ? g_a[0][(size_t)b * 512 + k] : g_a[1][(size_t)b * 512 + k - 512];
    }
    __syncthreads();

    int c0 = tid * 4;
    float4 acc = *(const float4*)&bh[c0];
#pragma unroll 4
    for (int k = 0; k < 1024; k++) {
        float4 w = *(const float4*)&Wh[(size_t)k * 512 + c0];
        float x = cat[k];
        acc.x += x * w.x; acc.y += x * w.y; acc.z += x * w.z; acc.w += x * w.w;
    }
    hid[c0 + 0] = fmaxf(acc.x, 0.f);
    hid[c0 + 1] = fmaxf(acc.y, 0.f);
    hid[c0 + 2] = fmaxf(acc.z, 0.f);
    hid[c0 + 3] = fmaxf(acc.w, 0.f);
    __syncthreads();

    float p0 = 0.f, p1 = 0.f;
#pragma unroll
    for (int i = 0; i < 4; i++) {
        float h = hid[c0 + i];
        p0 += h * Wout[(c0 + i) * 2 + 0];
        p1 += h * Wout[(c0 + i) * 2 + 1];
    }
#pragma unroll
    for (int off = 16; off > 0; off >>= 1) {
        p0 += __shfl_xor_sync(0xffffffffu, p0, off);
        p1 += __shfl_xor_sync(0xffffffffu, p1, off);
    }
    if (lane == 0) { red[0][warp] = p0; red[1][warp] = p1; }
    __syncthreads();
    if (tid == 0) {
        out[b * 2 + 0] = red[0][0] + red[0][1] + red[0][2] + red[0][3] + bout[0];
        out[b * 2 + 1] = red[1][0] + red[1][1] + red[1][2] + red[1][3] + bout[1];
    }
}

// ---------------- host: tensor maps + launch ----------------
typedef CUresult (*PFN_tmapEnc)(CUtensorMap*, CUtensorMapDataType, cuuint32_t, void*,
                                const cuuint64_t*, const cuuint64_t*, const cuuint32_t*,
                                const cuuint32_t*, CUtensorMapInterleave, CUtensorMapSwizzle,
                                CUtensorMapL2promotion, CUtensorMapFloatOOBfill);

static CUtensorMap s_maps[8];    // embedding GEMM: Ah0 Al0 Bh0 Bl0 Ah1 Al1 Bh1 Bl1
static CUtensorMap s_xmaps[8];   // xz GEMM:        Eh0 El0 Wh0 Wl0 Eh1 El1 Wh1 Wl1
static int s_init = 0;

static void make_map(PFN_tmapEnc fn, CUtensorMap* m, void* ptr,
                     unsigned long long kdim, unsigned long long rows, unsigned boxRows)
{
    cuuint64_t dims[2]    = {kdim, rows};
    cuuint64_t strides[1] = {kdim * 2ULL};
    cuuint32_t box[2]     = {64, boxRows};
    cuuint32_t es[2]      = {1, 1};
    fn(m, CU_TENSOR_MAP_DATA_TYPE_BFLOAT16, 2, ptr, dims, strides, box, es,
       CU_TENSOR_MAP_INTERLEAVE_NONE, CU_TENSOR_MAP_SWIZZLE_128B,
       CU_TENSOR_MAP_L2_PROMOTION_L2_128B, CU_TENSOR_MAP_FLOAT_OOB_FILL_NONE);
}

extern "C" void kernel_launch(void* const* d_in, const int* in_sizes, int n_in,
                              void* d_out, int out_size)
{
    const float* x1     = (const float*)d_in[0];
    const float* x2     = (const float*)d_in[1];
    const float* embed1 = (const float*)d_in[2];
    const float* embed2 = (const float*)d_in[3];
    const float* Wl1    = (const float*)d_in[4];
    const float* Wl2    = (const float*)d_in[5];
    const float* lng1   = (const float*)d_in[6];
    const float* lnb1   = (const float*)d_in[7];
    const float* lng2   = (const float*)d_in[8];
    const float* lnb2   = (const float*)d_in[9];
    const float* av1    = (const float*)d_in[10];
    const float* aWo1   = (const float*)d_in[11];
    const float* abo1   = (const float*)d_in[12];
    const float* av2    = (const float*)d_in[13];
    const float* aWo2   = (const float*)d_in[14];
    const float* abo2   = (const float*)d_in[15];
    const float* Wh     = (const float*)d_in[16];
    const float* bh     = (const float*)d_in[17];
    const float* Wout   = (const float*)d_in[18];
    const float* bout   = (const float*)d_in[19];
    float* out = (float*)d_out;

    if (!s_init) {
        cudaFuncSetAttribute(hmma_kernel,
                             cudaFuncAttributeMaxDynamicSharedMemorySize, SMEM_H);
        cudaFuncSetAttribute(hmma_xz_kernel,
                             cudaFuncAttributeMaxDynamicSharedMemorySize, SMEM_X);
        PFN_tmapEnc fn = nullptr;
        cudaDriverEntryPointQueryResult qr;
        cudaGetDriverEntryPoint("cuTensorMapEncodeTiled", (void**)&fn,
                                cudaEnableDefault, &qr);
        void *pxh, *pxl, *peh, *pel, *qeh, *qel, *qwh, *qwl;
        cudaGetSymbolAddress(&pxh, g_xhi);
        cudaGetSymbolAddress(&pxl, g_xlo);
        cudaGetSymbolAddress(&peh, g_ehT);
        cudaGetSymbolAddress(&pel, g_elT);
        cudaGetSymbolAddress(&qeh, g_ehi);
        cudaGetSymbolAddress(&qel, g_elo);
        cudaGetSymbolAddress(&qwh, g_wh);
        cudaGetSymbolAddress(&qwl, g_wl);
        size_t xs = (size_t)MROWS * KPAD * 2;
        size_t es = (size_t)NPAD * KPAD * 2;
        size_t ms = (size_t)MROWS * XK * 2;
        size_t ws = (size_t)512 * XK * 2;
        make_map(fn, &s_maps[0], (char*)pxh,      KPAD, MROWS, 64);
        make_map(fn, &s_maps[1], (char*)pxl,      KPAD, MROWS, 64);
        make_map(fn, &s_maps[2], (char*)peh,      KPAD, NPAD,  160);
        make_map(fn, &s_maps[3], (char*)pel,      KPAD, NPAD,  160);
        make_map(fn, &s_maps[4], (char*)pxh + xs, KPAD, MROWS, 64);
        make_map(fn, &s_maps[5], (char*)pxl + xs, KPAD, MROWS, 64);
        make_map(fn, &s_maps[6], (char*)peh + es, KPAD, NPAD,  160);
        make_map(fn, &s_maps[7], (char*)pel + es, KPAD, NPAD,  160);
        make_map(fn, &s_xmaps[0], (char*)qeh,      XK, MROWS, 64);
        make_map(fn, &s_xmaps[1], (char*)qel,      XK, MROWS, 64);
        make_map(fn, &s_xmaps[2], (char*)qwh,      XK, 512,   128);
        make_map(fn, &s_xmaps[3], (char*)qwl,      XK, 512,   128);
        make_map(fn, &s_xmaps[4], (char*)qeh + ms, XK, MROWS, 64);
        make_map(fn, &s_xmaps[5], (char*)qel + ms, XK, MROWS, 64);
        make_map(fn, &s_xmaps[6], (char*)qwh + ws, XK, 512,   128);
        make_map(fn, &s_xmaps[7], (char*)qwl + ws, XK, 512,   128);
        s_init = 1;
    }

    // 0) embed^T bf16 split   1) x bf16 split (float2 loads)   2) Wx^T bf16 split
    convE_kernel<<<dim3((NPAD*KPAD/8 + 255)/256, 2), 256>>>(embed1, embed2);
    convx_kernel<<<dim3((int)((size_t)MROWS*KPAD/8/256), 2), 256>>>(x1, x2);
    convW_kernel<<<dim3(80, 2), 256>>>(Wl1, Wl2);

    // 3) e-partials = x @ embed via HMMA + TMA
    hmma_kernel<<<dim3(4, 92, 2), 256, SMEM_H>>>(
        s_maps[0], s_maps[1], s_maps[2], s_maps[3],
        s_maps[4], s_maps[5], s_maps[6], s_maps[7]);

    // 4) e = p0+p1 -> bf16 hi/lo
    conv_e_kernel<<<dim3(920, 2), 256>>>();

    // 5) xz = e @ Wx via HMMA (profiled launch)
    hmma_xz_kernel<<<dim3(4, 92, 2), 256, SMEM_X>>>(
        s_xmaps[0], s_xmaps[1], s_xmaps[2], s_xmaps[3],
        s_xmaps[4], s_xmaps[5], s_xmaps[6], s_xmaps[7]);

    // 6) recurrence
    lstm_kernel<<<dim3(32, 2), 256>>>(Wl1, Wl2, lng1, lnb1, lng2, lnb2);
    // 7) attention
    attn_kernel<<<dim3(128, 2), 128>>>(av1, aWo1, abo1, av2, aWo2, abo2);
    // 8) head
    head_kernel<<<128, 128>>>(Wh, bh, Wout, bout, out);
}